// round 6
// baseline (speedup 1.0000x reference)
#include <cuda_runtime.h>
#include <cuda_bf16.h>
#include <math.h>
#include <stdint.h>

// ---------------------------------------------------------------------------
// Problem constants
// ---------------------------------------------------------------------------
#define BATCH    2
#define SEQ      2048
#define DMODEL   2048
#define DKV      512
#define DQ       1536
#define NHEADS   16
#define HDIM     128
#define ROWS     (BATCH*SEQ)            // 4096
#define QKDIM    256
#define SCALE    0.0625f                // 1/sqrt(256)

#define OUT_SZ   (BATCH*SEQ*DMODEL)
#define CKV_SZ   (BATCH*SEQ*DKV)

// ---------------------------------------------------------------------------
// Scratch
// ---------------------------------------------------------------------------
__device__ float g_cQ [ROWS*DQ];
__device__ float g_kC [ROWS*DMODEL];
__device__ float g_vT [BATCH*DMODEL*SEQ];        // V^T, s-permuted, tf32
__device__ float g_qC [ROWS*DMODEL];
__device__ float g_q  [BATCH*NHEADS*SEQ*QKDIM];  // tf32, scaled, kd-permuted
__device__ float g_k  [BATCH*NHEADS*SEQ*QKDIM];  // tf32, kd-permuted
__device__ float g_ctx[ROWS*DMODEL];

// fragment-order permutation within 16-element blocks of the reduction dim
__device__ __forceinline__ int perm16(int c) {
    return (c & ~15) | (((c & 3) << 2) | ((c >> 2) & 3));
}

// ---------------------------------------------------------------------------
// tf32 / cp.async helpers
// ---------------------------------------------------------------------------
__device__ __forceinline__ uint32_t f2tf32(float x) {
    uint32_t r;
    asm("cvt.rna.tf32.f32 %0, %1;" : "=r"(r) : "f"(x));
    return r;
}
__device__ __forceinline__ float f2tf32f(float x) {
    return __uint_as_float(f2tf32(x));
}

__device__ __forceinline__ void mma_tf32(float c[4],
                                         const uint32_t a[4],
                                         const uint32_t b[2]) {
    asm volatile(
        "mma.sync.aligned.m16n8k8.row.col.f32.tf32.tf32.f32 "
        "{%0,%1,%2,%3}, {%4,%5,%6,%7}, {%8,%9}, {%0,%1,%2,%3};\n"
        : "+f"(c[0]), "+f"(c[1]), "+f"(c[2]), "+f"(c[3])
        : "r"(a[0]), "r"(a[1]), "r"(a[2]), "r"(a[3]),
          "r"(b[0]), "r"(b[1]));
}

__device__ __forceinline__ void cp_async16(float* smem_dst, const float* gsrc) {
    uint32_t sa = (uint32_t)__cvta_generic_to_shared(smem_dst);
    asm volatile("cp.async.cg.shared.global [%0], [%1], 16;\n"
                 :: "r"(sa), "l"(gsrc));
}
__device__ __forceinline__ void cp_commit() {
    asm volatile("cp.async.commit_group;\n" ::: "memory");
}
__device__ __forceinline__ void cp_wait1() {
    asm volatile("cp.async.wait_group 1;\n" ::: "memory");
}
__device__ __forceinline__ void cp_wait2() {
    asm volatile("cp.async.wait_group 2;\n" ::: "memory");
}

// ---------------------------------------------------------------------------
// Pipelined TF32 GEMM.  mode: 0 = plain store, 1 = tf32-round store,
//                             2 = tf32-round + store transposed/perm to vT
// ---------------------------------------------------------------------------
#define GSTAGES 3
#define GBK     32
#define A_LD    36
#define B_LD    136
#define STAGE_FLOATS (128*A_LD + GBK*B_LD)
#define GEMM_SMEM    (GSTAGES*STAGE_FLOATS*4)

__device__ __forceinline__ void g_load_stage(
    float* As, float* Bs,
    const float* __restrict__ Ab, const float* __restrict__ Bb,
    int k0, int K, int N, int tid)
{
#pragma unroll
    for (int i = 0; i < 8; i++) {
        int c = tid + 128 * i;
        int am = c >> 3, ak = (c & 7) * 4;
        cp_async16(As + am * A_LD + ak, Ab + (size_t)am * K + k0 + ak);
    }
#pragma unroll
    for (int i = 0; i < 8; i++) {
        int c = tid + 128 * i;
        int bk = c >> 5, bn = (c & 31) * 4;
        cp_async16(Bs + bk * B_LD + bn, Bb + (size_t)(k0 + bk) * N + bn);
    }
}

__global__ __launch_bounds__(128, 2) void tf32_gemm_pipe(
    int M, int N, int K,
    const float* __restrict__ A, const float* __restrict__ B,
    const float* __restrict__ bias, float* __restrict__ C, int mode)
{
    extern __shared__ float gsm[];

    const int tid  = threadIdx.x;
    const int bx   = blockIdx.x, by = blockIdx.y;
    const int warp = tid >> 5, lane = tid & 31;
    const int wm   = (warp >> 1) * 64;
    const int wn   = (warp & 1) * 64;
    const int g    = lane >> 2;
    const int tg   = lane & 3;

    const float* Ab = A + (size_t)(by * 128) * K;
    const float* Bb = B + bx * 128;

    float acc[4][8][4];
#pragma unroll
    for (int mt = 0; mt < 4; mt++)
#pragma unroll
        for (int nt = 0; nt < 8; nt++)
#pragma unroll
            for (int i = 0; i < 4; i++) acc[mt][nt][i] = 0.f;

#pragma unroll
    for (int s = 0; s < GSTAGES; s++) {
        if (s * GBK < K)
            g_load_stage(gsm + s * STAGE_FLOATS,
                         gsm + s * STAGE_FLOATS + 128 * A_LD,
                         Ab, Bb, s * GBK, K, N, tid);
        cp_commit();
    }

    int rs = 0;
    for (int k0 = 0; k0 < K; k0 += GBK) {
        cp_wait2();
        __syncthreads();

        float* As = gsm + rs * STAGE_FLOATS;
        float* Bs = As + 128 * A_LD;

#pragma unroll
        for (int ks = 0; ks < GBK; ks += 8) {
            uint32_t af[4][4], bf[8][2];
#pragma unroll
            for (int mt = 0; mt < 4; mt++) {
                const float* ab = As + (wm + mt * 16 + g) * A_LD + ks + tg;
                af[mt][0] = f2tf32(ab[0]);
                af[mt][2] = f2tf32(ab[4]);
                af[mt][1] = f2tf32(ab[8 * A_LD]);
                af[mt][3] = f2tf32(ab[8 * A_LD + 4]);
            }
#pragma unroll
            for (int nt = 0; nt < 8; nt++) {
                int n0 = wn + nt * 8;
                bf[nt][0] = f2tf32(Bs[(ks + tg) * B_LD + n0 + g]);
                bf[nt][1] = f2tf32(Bs[(ks + tg + 4) * B_LD + n0 + g]);
            }
#pragma unroll
            for (int mt = 0; mt < 4; mt++)
#pragma unroll
                for (int nt = 0; nt < 8; nt++)
                    mma_tf32(acc[mt][nt], af[mt], bf[nt]);
        }

        __syncthreads();
        int kl = k0 + GSTAGES * GBK;
        if (kl < K)
            g_load_stage(As, Bs, Ab, Bb, kl, K, N, tid);
        cp_commit();
        rs = rs + 1; if (rs == GSTAGES) rs = 0;
    }

#pragma unroll
    for (int mt = 0; mt < 4; mt++) {
        int r_lo = by * 128 + wm + mt * 16 + g;
        int r_hi = r_lo + 8;
#pragma unroll
        for (int nt = 0; nt < 8; nt++) {
            int col = bx * 128 + wn + nt * 8 + 2 * tg;
            float b0 = bias[col], b1 = bias[col + 1];
            float v00 = acc[mt][nt][0] + b0, v01 = acc[mt][nt][1] + b1;
            float v10 = acc[mt][nt][2] + b0, v11 = acc[mt][nt][3] + b1;
            if (mode == 2) {
                // store transposed + s-permuted tf32 into vT[b][col][s']
                int blo = r_lo >> 11, slo = perm16(r_lo & 2047);
                int bhi = r_hi >> 11, shi = perm16(r_hi & 2047);
                C[((size_t)blo * N + col)     * SEQ + slo] = f2tf32f(v00);
                C[((size_t)blo * N + col + 1) * SEQ + slo] = f2tf32f(v01);
                C[((size_t)bhi * N + col)     * SEQ + shi] = f2tf32f(v10);
                C[((size_t)bhi * N + col + 1) * SEQ + shi] = f2tf32f(v11);
            } else {
                float2 lo = make_float2(v00, v01);
                float2 hi = make_float2(v10, v11);
                if (mode == 1) {
                    lo.x = f2tf32f(lo.x); lo.y = f2tf32f(lo.y);
                    hi.x = f2tf32f(hi.x); hi.y = f2tf32f(hi.y);
                }
                *(float2*)(&C[(size_t)r_lo * N + col])     = lo;
                *(float2*)(&C[(size_t)r_hi * N + col])     = hi;
            }
        }
    }
}

// ---------------------------------------------------------------------------
// Pack q (tf32, scaled, kd-permuted)
// ---------------------------------------------------------------------------
__global__ __launch_bounds__(256) void pack_q_kernel(
    const float* __restrict__ qC, float* __restrict__ q)
{
    int gid = blockIdx.x * blockDim.x + threadIdx.x;
    int i = gid & 63;
    int s = (gid >> 6) & (SEQ - 1);
    int h = (gid >> 17) & (NHEADS - 1);
    int b = gid >> 21;

    const float* src = qC + ((size_t)(b * SEQ + s)) * DMODEL + h * HDIM;
    float x1 = src[2 * i], x2 = src[2 * i + 1];

    float inv = powf(10000.0f, -(float)(2 * i) / 128.0f);
    float ang = (float)s * inv;
    float sn, cs; sincosf(ang, &sn, &cs);

    float* dst = q + (((size_t)(b * NHEADS + h)) * SEQ + s) * QKDIM;
    dst[perm16(2 * i)]       = f2tf32f(x1 * SCALE);
    dst[perm16(2 * i + 1)]   = f2tf32f(x2 * SCALE);
    dst[perm16(128 + 2 * i)] = f2tf32f((x1 * cs - x2 * sn) * SCALE);
    dst[perm16(129 + 2 * i)] = f2tf32f((x1 * sn + x2 * cs) * SCALE);
}

// ---------------------------------------------------------------------------
// Pack k (tf32, kd-permuted)
// ---------------------------------------------------------------------------
__global__ __launch_bounds__(256) void pack_k_kernel(
    const float* __restrict__ kC, const float* __restrict__ kr,
    float* __restrict__ k)
{
    int gid = blockIdx.x * blockDim.x + threadIdx.x;
    int i = gid & 63;
    int s = (gid >> 6) & (SEQ - 1);
    int h = (gid >> 17) & (NHEADS - 1);
    int b = gid >> 21;

    size_t soff = ((size_t)(b * SEQ + s)) * DMODEL + h * HDIM;
    const float* raw = kC + soff;
    const float* rot = kr + soff;
    float x1 = rot[2 * i], x2 = rot[2 * i + 1];

    float inv = powf(10000.0f, -(float)(2 * i) / 128.0f);
    float ang = (float)s * inv;
    float sn, cs; sincosf(ang, &sn, &cs);

    float* dst = k + (((size_t)(b * NHEADS + h)) * SEQ + s) * QKDIM;
    dst[perm16(2 * i)]       = f2tf32f(raw[2 * i]);
    dst[perm16(2 * i + 1)]   = f2tf32f(raw[2 * i + 1]);
    dst[perm16(128 + 2 * i)] = f2tf32f(x1 * cs - x2 * sn);
    dst[perm16(129 + 2 * i)] = f2tf32f(x1 * sn + x2 * cs);
}

// ---------------------------------------------------------------------------
// TF32 flash attention.  BM=BN=64, 128 threads, 4 warps over M.
// All fragment loads are LDS.128 via permuted reduction-dim layouts.
// Each CTA processes two q-tiles (qt, 31-qt) for uniform work.
// ---------------------------------------------------------------------------
#define QS_LD 272
#define KS_LD 272
#define VT_LD 80
#define PS_LD 80
#define FL_SMEM ((64*QS_LD + 64*KS_LD + 128*VT_LD + 64*PS_LD) * 4)

__global__ __launch_bounds__(128, 1) void flash_tf32(
    const float* __restrict__ q,    // [B,H,S,256] tf32, scaled, kd-perm
    const float* __restrict__ kk,   // [B,H,S,256] tf32, kd-perm
    const float* __restrict__ vT,   // [B,2048,S]  tf32, s-perm
    float* __restrict__ ctx)        // [B,S,2048]
{
    extern __shared__ float sm[];
    float* qs = sm;
    float* ks = qs + 64 * QS_LD;
    float* vs = ks + 64 * KS_LD;
    float* ps = vs + 128 * VT_LD;

    const int tid  = threadIdx.x;
    const int warp = tid >> 5, lane = tid & 31;
    const int g    = lane >> 2;     // 0..7
    const int tg   = lane & 3;      // 0..3
    const int wm   = warp * 16;

    const int bh = blockIdx.y;
    const int b = bh >> 4, h = bh & 15;

    const float* vtb_base = vT + ((size_t)b * DMODEL + h * HDIM) * SEQ;

    for (int pass = 0; pass < 2; pass++) {
        const int qt = pass ? (31 - blockIdx.x) : blockIdx.x;

        // ---- issue q + k(0) as one group, v(0) as another ----
        const float* qbase = q + ((size_t)bh * SEQ + qt * 64) * QKDIM;
#pragma unroll
        for (int i = 0; i < 32; i++) {
            int c = tid + 128 * i;
            int r = c >> 6, c4 = (c & 63) * 4;
            cp_async16(qs + r * QS_LD + c4, qbase + (size_t)r * QKDIM + c4);
        }
        const float* kb0 = kk + ((size_t)bh * SEQ) * QKDIM;
#pragma unroll
        for (int i = 0; i < 32; i++) {
            int c = tid + 128 * i;
            int r = c >> 6, c4 = (c & 63) * 4;
            cp_async16(ks + r * KS_LD + c4, kb0 + (size_t)r * QKDIM + c4);
        }
        cp_commit();
#pragma unroll
        for (int i = 0; i < 16; i++) {
            int c = tid + 128 * i;
            int r = c >> 4, s4 = (c & 15) * 4;
            cp_async16(vs + r * VT_LD + s4, vtb_base + (size_t)r * SEQ + s4);
        }
        cp_commit();

        float m0 = -1e30f, m1 = -1e30f, l0 = 0.f, l1 = 0.f;
        float oacc[16][4];
#pragma unroll
        for (int nt = 0; nt < 16; nt++)
#pragma unroll
            for (int i = 0; i < 4; i++) oacc[nt][i] = 0.f;

        const int rg0 = qt * 64 + wm + g;
        const int rg1 = rg0 + 8;

        for (int kt = 0; kt <= qt; kt++) {
            cp_wait1();
            __syncthreads();

            // ---- S = Q . K^T ----
            float sacc[8][4];
#pragma unroll
            for (int nt = 0; nt < 8; nt++)
#pragma unroll
                for (int i = 0; i < 4; i++) sacc[nt][i] = 0.f;

#pragma unroll
            for (int kb = 0; kb < 16; kb++) {
                float4 qa = *(const float4*)(qs + (wm + g)     * QS_LD + kb * 16 + 4 * tg);
                float4 qb = *(const float4*)(qs + (wm + g + 8) * QS_LD + kb * 16 + 4 * tg);
                uint32_t afA[4] = { __float_as_uint(qa.x), __float_as_uint(qb.x),
                                    __float_as_uint(qa.y), __float_as_uint(qb.y) };
                uint32_t afB[4] = { __float_as_uint(qa.z), __float_as_uint(qb.z),
                                    __float_as_uint(qa.w), __float_as_uint(qb.w) };
#pragma unroll
                for (int nt = 0; nt < 8; nt++) {
                    float4 kv = *(const float4*)(ks + (8 * nt + g) * KS_LD + kb * 16 + 4 * tg);
                    uint32_t bfA[2] = { __float_as_uint(kv.x), __float_as_uint(kv.y) };
                    uint32_t bfB[2] = { __float_as_uint(kv.z), __float_as_uint(kv.w) };
                    mma_tf32(sacc[nt], afA, bfA);
                    mma_tf32(sacc[nt], afB, bfB);
                }
            }

            // ---- causal mask ----
            if (kt == qt) {
                int cb = kt * 64 + 2 * tg;
#pragma unroll
                for (int nt = 0; nt < 8; nt++) {
                    int c0 = cb + 8 * nt, c1 = c0 + 1;
                    if (c0 > rg0) sacc[nt][0] = -1e30f;
                    if (c1 > rg0) sacc[nt][1] = -1e30f;
                    if (c0 > rg1) sacc[nt][2] = -1e30f;
                    if (c1 > rg1) sacc[nt][3] = -1e30f;
                }
            }

            // ---- online softmax ----
            float tA = -1e30f, tB = -1e30f;
#pragma unroll
            for (int nt = 0; nt < 8; nt++) {
                tA = fmaxf(tA, fmaxf(sacc[nt][0], sacc[nt][1]));
                tB = fmaxf(tB, fmaxf(sacc[nt][2], sacc[nt][3]));
            }
            tA = fmaxf(tA, __shfl_xor_sync(0xffffffffu, tA, 1));
            tA = fmaxf(tA, __shfl_xor_sync(0xffffffffu, tA, 2));
            tB = fmaxf(tB, __shfl_xor_sync(0xffffffffu, tB, 1));
            tB = fmaxf(tB, __shfl_xor_sync(0xffffffffu, tB, 2));

            float mn0 = fmaxf(m0, tA), mn1 = fmaxf(m1, tB);
            float f0 = __expf(m0 - mn0), f1 = __expf(m1 - mn1);
            m0 = mn0; m1 = mn1;

            float sum0 = 0.f, sum1 = 0.f;
            float* pr0 = ps + (wm + g) * PS_LD;
            float* pr1 = ps + (wm + g + 8) * PS_LD;
#pragma unroll
            for (int nt = 0; nt < 8; nt++) {
                int c0 = 8 * nt + 2 * tg, c1 = c0 + 1;
                float p0 = __expf(sacc[nt][0] - mn0);
                float p1 = __expf(sacc[nt][1] - mn0);
                float p2 = __expf(sacc[nt][2] - mn1);
                float p3 = __expf(sacc[nt][3] - mn1);
                sum0 += p0 + p1;
                sum1 += p2 + p3;
                pr0[perm16(c0)] = f2tf32f(p0);
                pr0[perm16(c1)] = f2tf32f(p1);
                pr1[perm16(c0)] = f2tf32f(p2);
                pr1[perm16(c1)] = f2tf32f(p3);
            }
            sum0 += __shfl_xor_sync(0xffffffffu, sum0, 1);
            sum0 += __shfl_xor_sync(0xffffffffu, sum0, 2);
            sum1 += __shfl_xor_sync(0xffffffffu, sum1, 1);
            sum1 += __shfl_xor_sync(0xffffffffu, sum1, 2);
            l0 = l0 * f0 + sum0;
            l1 = l1 * f1 + sum1;

            __syncthreads();

            // ---- prefetch k(kt+1) (overlaps P@V) ----
            if (kt < qt) {
                const float* kb = kk + ((size_t)bh * SEQ + (kt + 1) * 64) * QKDIM;
#pragma unroll
                for (int i = 0; i < 32; i++) {
                    int c = tid + 128 * i;
                    int r = c >> 6, c4 = (c & 63) * 4;
                    cp_async16(ks + r * KS_LD + c4, kb + (size_t)r * QKDIM + c4);
                }
            }
            cp_commit();

            cp_wait1();
            __syncthreads();

            // ---- rescale O, then O += P @ V ----
#pragma unroll
            for (int nt = 0; nt < 16; nt++) {
                oacc[nt][0] *= f0; oacc[nt][1] *= f0;
                oacc[nt][2] *= f1; oacc[nt][3] *= f1;
            }
#pragma unroll
            for (int kb = 0; kb < 4; kb++) {
                float4 pa = *(const float4*)(ps + (wm + g)     * PS_LD + kb * 16 + 4 * tg);
                float4 pb = *(const float4*)(ps + (wm + g + 8) * PS_LD + kb * 16 + 4 * tg);
                uint32_t afA[4] = { __float_as_uint(pa.x), __float_as_uint(pb.x),
                                    __float_as_uint(pa.y), __float_as_uint(pb.y) };
                uint32_t afB[4] = { __float_as_uint(pa.z), __float_as_uint(pb.z),
                                    __float_as_uint(pa.w), __float_as_uint(pb.w) };
#pragma unroll
                for (int nt = 0; nt < 16; nt++) {
                    float4 vv = *(const float4*)(vs + (8 * nt + g) * VT_LD + kb * 16 + 4 * tg);
                    uint32_t bfA[2] = { __float_as_uint(vv.x), __float_as_uint(vv.y) };
                    uint32_t bfB[2] = { __float_as_uint(vv.z), __float_as_uint(vv.w) };
                    mma_tf32(oacc[nt], afA, bfA);
                    mma_tf32(oacc[nt], afB, bfB);
                }
            }

            __syncthreads();

            // ---- prefetch v(kt+1) (overlaps next S) ----
            if (kt < qt) {
                const float* vtb = vtb_base + (size_t)(kt + 1) * 64;
#pragma unroll
                for (int i = 0; i < 16; i++) {
                    int c = tid + 128 * i;
                    int r = c >> 4, s4 = (c & 15) * 4;
                    cp_async16(vs + r * VT_LD + s4, vtb + (size_t)r * SEQ + s4);
                }
            }
            cp_commit();
        }

        // ---- epilogue ----
        float inv0 = 1.f / l0, inv1 = 1.f / l1;
        float* o0 = ctx + ((size_t)b * SEQ + rg0) * DMODEL + h * HDIM + 2 * tg;
        float* o1 = ctx + ((size_t)b * SEQ + rg1) * DMODEL + h * HDIM + 2 * tg;
#pragma unroll
        for (int nt = 0; nt < 16; nt++) {
            *(float2*)(o0 + 8 * nt) = make_float2(oacc[nt][0] * inv0, oacc[nt][1] * inv0);
            *(float2*)(o1 + 8 * nt) = make_float2(oacc[nt][2] * inv1, oacc[nt][3] * inv1);
        }
    }
}

// ---------------------------------------------------------------------------
// Launch
// ---------------------------------------------------------------------------
extern "C" void kernel_launch(void* const* d_in, const int* in_sizes, int n_in,
                              void* d_out, int out_size)
{
    const float* h     = (const float*)d_in[0];
    const float* W_DKV = (const float*)d_in[1];
    const float* b_DKV = (const float*)d_in[2];
    const float* W_UK  = (const float*)d_in[3];
    const float* b_UK  = (const float*)d_in[4];
    const float* W_UV  = (const float*)d_in[5];
    const float* b_UV  = (const float*)d_in[6];
    const float* W_DQ  = (const float*)d_in[7];
    const float* b_DQ  = (const float*)d_in[8];
    const float* W_UQ  = (const float*)d_in[9];
    const float* b_UQ  = (const float*)d_in[10];
    const float* W_KR  = (const float*)d_in[11];
    const float* b_KR  = (const float*)d_in[12];
    const float* W_O   = (const float*)d_in[13];
    const float* b_O   = (const float*)d_in[14];

    float* out = (float*)d_out;
    float* cKV = out + OUT_SZ;
    float* kr  = cKV + CKV_SZ;

    float *p_cQ, *p_kC, *p_vT, *p_qC, *p_q, *p_k, *p_ctx;
    cudaGetSymbolAddress((void**)&p_cQ,  g_cQ);
    cudaGetSymbolAddress((void**)&p_kC,  g_kC);
    cudaGetSymbolAddress((void**)&p_vT,  g_vT);
    cudaGetSymbolAddress((void**)&p_qC,  g_qC);
    cudaGetSymbolAddress((void**)&p_q,   g_q);
    cudaGetSymbolAddress((void**)&p_k,   g_k);
    cudaGetSymbolAddress((void**)&p_ctx, g_ctx);

    cudaFuncSetAttribute(tf32_gemm_pipe,
                         cudaFuncAttributeMaxDynamicSharedMemorySize, GEMM_SMEM);
    cudaFuncSetAttribute(flash_tf32,
                         cudaFuncAttributeMaxDynamicSharedMemorySize, FL_SMEM);

    // projections
    tf32_gemm_pipe<<<dim3(DKV/128,    ROWS/128), 128, GEMM_SMEM>>>(ROWS, DKV,    DMODEL, h,    W_DKV, b_DKV, cKV, 0);
    tf32_gemm_pipe<<<dim3(DMODEL/128, ROWS/128), 128, GEMM_SMEM>>>(ROWS, DMODEL, DMODEL, h,    W_KR,  b_KR,  kr, 0);
    tf32_gemm_pipe<<<dim3(DQ/128,     ROWS/128), 128, GEMM_SMEM>>>(ROWS, DQ,     DMODEL, h,    W_DQ,  b_DQ,  p_cQ, 0);
    tf32_gemm_pipe<<<dim3(DMODEL/128, ROWS/128), 128, GEMM_SMEM>>>(ROWS, DMODEL, DKV,    cKV,  W_UK,  b_UK,  p_kC, 0);
    tf32_gemm_pipe<<<dim3(DMODEL/128, ROWS/128), 128, GEMM_SMEM>>>(ROWS, DMODEL, DKV,    cKV,  W_UV,  b_UV,  p_vT, 2);
    tf32_gemm_pipe<<<dim3(DMODEL/128, ROWS/128), 128, GEMM_SMEM>>>(ROWS, DMODEL, DQ,     p_cQ, W_UQ,  b_UQ,  p_qC, 0);

    // rope + repack (tf32, permuted)
    int pack_threads = BATCH * NHEADS * SEQ * 64;
    pack_q_kernel<<<pack_threads / 256, 256>>>(p_qC, p_q);
    pack_k_kernel<<<pack_threads / 256, 256>>>(p_kC, kr, p_k);

    // attention
    flash_tf32<<<dim3(16, BATCH*NHEADS), 128, FL_SMEM>>>(p_q, p_k, p_vT, p_ctx);

    // output projection
    tf32_gemm_pipe<<<dim3(DMODEL/128, ROWS/128), 128, GEMM_SMEM>>>(ROWS, DMODEL, DMODEL, p_ctx, W_O, b_O, out, 0);
}

// round 7
// speedup vs baseline: 1.0273x; 1.0273x over previous
#include <cuda_runtime.h>
#include <cuda_bf16.h>
#include <math.h>
#include <stdint.h>

// ---------------------------------------------------------------------------
// Problem constants
// ---------------------------------------------------------------------------
#define BATCH    2
#define SEQ      2048
#define DMODEL   2048
#define DKV      512
#define DQ       1536
#define NHEADS   16
#define HDIM     128
#define ROWS     (BATCH*SEQ)            // 4096
#define QKDIM    256
#define SCALE    0.0625f                // 1/sqrt(256)

#define OUT_SZ   (BATCH*SEQ*DMODEL)
#define CKV_SZ   (BATCH*SEQ*DKV)

// ---------------------------------------------------------------------------
// Scratch
// ---------------------------------------------------------------------------
__device__ float g_cQ [ROWS*DQ];
__device__ float g_kC [ROWS*DMODEL];
__device__ float g_vT [BATCH*DMODEL*SEQ];        // V^T, s-permuted, tf32
__device__ float g_qC [ROWS*DMODEL];
__device__ float g_q  [BATCH*NHEADS*SEQ*QKDIM];  // tf32, scaled, kd-permuted
__device__ float g_k  [BATCH*NHEADS*SEQ*QKDIM];  // tf32, kd-permuted
__device__ float g_ctx[ROWS*DMODEL];

// fragment-order permutation within 16-element blocks of the reduction dim
__device__ __forceinline__ int perm16(int c) {
    return (c & ~15) | (((c & 3) << 2) | ((c >> 2) & 3));
}

// ---------------------------------------------------------------------------
// tf32 / cp.async helpers
// ---------------------------------------------------------------------------
__device__ __forceinline__ uint32_t f2tf32(float x) {
    uint32_t r;
    asm("cvt.rna.tf32.f32 %0, %1;" : "=r"(r) : "f"(x));
    return r;
}
__device__ __forceinline__ float f2tf32f(float x) {
    return __uint_as_float(f2tf32(x));
}

__device__ __forceinline__ void mma_tf32(float c[4],
                                         const uint32_t a[4],
                                         const uint32_t b[2]) {
    asm volatile(
        "mma.sync.aligned.m16n8k8.row.col.f32.tf32.tf32.f32 "
        "{%0,%1,%2,%3}, {%4,%5,%6,%7}, {%8,%9}, {%0,%1,%2,%3};\n"
        : "+f"(c[0]), "+f"(c[1]), "+f"(c[2]), "+f"(c[3])
        : "r"(a[0]), "r"(a[1]), "r"(a[2]), "r"(a[3]),
          "r"(b[0]), "r"(b[1]));
}

__device__ __forceinline__ void cp_async16(float* smem_dst, const float* gsrc) {
    uint32_t sa = (uint32_t)__cvta_generic_to_shared(smem_dst);
    asm volatile("cp.async.cg.shared.global [%0], [%1], 16;\n"
                 :: "r"(sa), "l"(gsrc));
}
__device__ __forceinline__ void cp_commit() {
    asm volatile("cp.async.commit_group;\n" ::: "memory");
}
__device__ __forceinline__ void cp_wait1() {
    asm volatile("cp.async.wait_group 1;\n" ::: "memory");
}
__device__ __forceinline__ void cp_wait2() {
    asm volatile("cp.async.wait_group 2;\n" ::: "memory");
}

// ---------------------------------------------------------------------------
// Pipelined TF32 GEMM.  mode: 0 = plain store, 1 = tf32-round store,
//                             2 = tf32-round + store transposed/perm to vT
// ---------------------------------------------------------------------------
#define GSTAGES 3
#define GBK     32
#define A_LD    36
#define B_LD    136
#define STAGE_FLOATS (128*A_LD + GBK*B_LD)
#define GEMM_SMEM    (GSTAGES*STAGE_FLOATS*4)

__device__ __forceinline__ void g_load_stage(
    float* As, float* Bs,
    const float* __restrict__ Ab, const float* __restrict__ Bb,
    int k0, int K, int N, int tid)
{
#pragma unroll
    for (int i = 0; i < 8; i++) {
        int c = tid + 128 * i;
        int am = c >> 3, ak = (c & 7) * 4;
        cp_async16(As + am * A_LD + ak, Ab + (size_t)am * K + k0 + ak);
    }
#pragma unroll
    for (int i = 0; i < 8; i++) {
        int c = tid + 128 * i;
        int bk = c >> 5, bn = (c & 31) * 4;
        cp_async16(Bs + bk * B_LD + bn, Bb + (size_t)(k0 + bk) * N + bn);
    }
}

__global__ __launch_bounds__(128, 2) void tf32_gemm_pipe(
    int M, int N, int K,
    const float* __restrict__ A, const float* __restrict__ B,
    const float* __restrict__ bias, float* __restrict__ C, int mode)
{
    extern __shared__ float gsm[];

    const int tid  = threadIdx.x;
    const int bx   = blockIdx.x, by = blockIdx.y;
    const int warp = tid >> 5, lane = tid & 31;
    const int wm   = (warp >> 1) * 64;
    const int wn   = (warp & 1) * 64;
    const int g    = lane >> 2;
    const int tg   = lane & 3;

    const float* Ab = A + (size_t)(by * 128) * K;
    const float* Bb = B + bx * 128;

    float acc[4][8][4];
#pragma unroll
    for (int mt = 0; mt < 4; mt++)
#pragma unroll
        for (int nt = 0; nt < 8; nt++)
#pragma unroll
            for (int i = 0; i < 4; i++) acc[mt][nt][i] = 0.f;

#pragma unroll
    for (int s = 0; s < GSTAGES; s++) {
        if (s * GBK < K)
            g_load_stage(gsm + s * STAGE_FLOATS,
                         gsm + s * STAGE_FLOATS + 128 * A_LD,
                         Ab, Bb, s * GBK, K, N, tid);
        cp_commit();
    }

    int rs = 0;
    for (int k0 = 0; k0 < K; k0 += GBK) {
        cp_wait2();
        __syncthreads();

        float* As = gsm + rs * STAGE_FLOATS;
        float* Bs = As + 128 * A_LD;

#pragma unroll
        for (int ks = 0; ks < GBK; ks += 8) {
            uint32_t af[4][4], bf[8][2];
#pragma unroll
            for (int mt = 0; mt < 4; mt++) {
                const float* ab = As + (wm + mt * 16 + g) * A_LD + ks + tg;
                af[mt][0] = f2tf32(ab[0]);
                af[mt][2] = f2tf32(ab[4]);
                af[mt][1] = f2tf32(ab[8 * A_LD]);
                af[mt][3] = f2tf32(ab[8 * A_LD + 4]);
            }
#pragma unroll
            for (int nt = 0; nt < 8; nt++) {
                int n0 = wn + nt * 8;
                bf[nt][0] = f2tf32(Bs[(ks + tg) * B_LD + n0 + g]);
                bf[nt][1] = f2tf32(Bs[(ks + tg + 4) * B_LD + n0 + g]);
            }
#pragma unroll
            for (int mt = 0; mt < 4; mt++)
#pragma unroll
                for (int nt = 0; nt < 8; nt++)
                    mma_tf32(acc[mt][nt], af[mt], bf[nt]);
        }

        __syncthreads();
        int kl = k0 + GSTAGES * GBK;
        if (kl < K)
            g_load_stage(As, Bs, Ab, Bb, kl, K, N, tid);
        cp_commit();
        rs = rs + 1; if (rs == GSTAGES) rs = 0;
    }

#pragma unroll
    for (int mt = 0; mt < 4; mt++) {
        int r_lo = by * 128 + wm + mt * 16 + g;
        int r_hi = r_lo + 8;
#pragma unroll
        for (int nt = 0; nt < 8; nt++) {
            int col = bx * 128 + wn + nt * 8 + 2 * tg;
            float b0 = bias[col], b1 = bias[col + 1];
            float v00 = acc[mt][nt][0] + b0, v01 = acc[mt][nt][1] + b1;
            float v10 = acc[mt][nt][2] + b0, v11 = acc[mt][nt][3] + b1;
            if (mode == 2) {
                int blo = r_lo >> 11, slo = perm16(r_lo & 2047);
                int bhi = r_hi >> 11, shi = perm16(r_hi & 2047);
                C[((size_t)blo * N + col)     * SEQ + slo] = f2tf32f(v00);
                C[((size_t)blo * N + col + 1) * SEQ + slo] = f2tf32f(v01);
                C[((size_t)bhi * N + col)     * SEQ + shi] = f2tf32f(v10);
                C[((size_t)bhi * N + col + 1) * SEQ + shi] = f2tf32f(v11);
            } else {
                float2 lo = make_float2(v00, v01);
                float2 hi = make_float2(v10, v11);
                if (mode == 1) {
                    lo.x = f2tf32f(lo.x); lo.y = f2tf32f(lo.y);
                    hi.x = f2tf32f(hi.x); hi.y = f2tf32f(hi.y);
                }
                *(float2*)(&C[(size_t)r_lo * N + col])     = lo;
                *(float2*)(&C[(size_t)r_hi * N + col])     = hi;
            }
        }
    }
}

// ---------------------------------------------------------------------------
// Pack q (tf32, scaled, kd-permuted)
// ---------------------------------------------------------------------------
__global__ __launch_bounds__(256) void pack_q_kernel(
    const float* __restrict__ qC, float* __restrict__ q)
{
    int gid = blockIdx.x * blockDim.x + threadIdx.x;
    int i = gid & 63;
    int s = (gid >> 6) & (SEQ - 1);
    int h = (gid >> 17) & (NHEADS - 1);
    int b = gid >> 21;

    const float* src = qC + ((size_t)(b * SEQ + s)) * DMODEL + h * HDIM;
    float x1 = src[2 * i], x2 = src[2 * i + 1];

    float inv = powf(10000.0f, -(float)(2 * i) / 128.0f);
    float ang = (float)s * inv;
    float sn, cs; sincosf(ang, &sn, &cs);

    float* dst = q + (((size_t)(b * NHEADS + h)) * SEQ + s) * QKDIM;
    dst[perm16(2 * i)]       = f2tf32f(x1 * SCALE);
    dst[perm16(2 * i + 1)]   = f2tf32f(x2 * SCALE);
    dst[perm16(128 + 2 * i)] = f2tf32f((x1 * cs - x2 * sn) * SCALE);
    dst[perm16(129 + 2 * i)] = f2tf32f((x1 * sn + x2 * cs) * SCALE);
}

// ---------------------------------------------------------------------------
// Pack k (tf32, kd-permuted)
// ---------------------------------------------------------------------------
__global__ __launch_bounds__(256) void pack_k_kernel(
    const float* __restrict__ kC, const float* __restrict__ kr,
    float* __restrict__ k)
{
    int gid = blockIdx.x * blockDim.x + threadIdx.x;
    int i = gid & 63;
    int s = (gid >> 6) & (SEQ - 1);
    int h = (gid >> 17) & (NHEADS - 1);
    int b = gid >> 21;

    size_t soff = ((size_t)(b * SEQ + s)) * DMODEL + h * HDIM;
    const float* raw = kC + soff;
    const float* rot = kr + soff;
    float x1 = rot[2 * i], x2 = rot[2 * i + 1];

    float inv = powf(10000.0f, -(float)(2 * i) / 128.0f);
    float ang = (float)s * inv;
    float sn, cs; sincosf(ang, &sn, &cs);

    float* dst = k + (((size_t)(b * NHEADS + h)) * SEQ + s) * QKDIM;
    dst[perm16(2 * i)]       = f2tf32f(raw[2 * i]);
    dst[perm16(2 * i + 1)]   = f2tf32f(raw[2 * i + 1]);
    dst[perm16(128 + 2 * i)] = f2tf32f(x1 * cs - x2 * sn);
    dst[perm16(129 + 2 * i)] = f2tf32f(x1 * sn + x2 * cs);
}

// ---------------------------------------------------------------------------
// TF32 flash attention.  BM=BN=64, 256 threads (8 warps: 4 over M, 2 over
// col/d halves).  Cross-warp-pair softmax via smem stats (2 syncs).
// Each CTA processes two q-tiles (qt, 31-qt) for uniform work.
// ---------------------------------------------------------------------------
#define QS_LD 272
#define KS_LD 272
#define VT_LD 80
#define PS_LD 80
#define ST_LD 72
#define FL_SMEM ((64*QS_LD + 64*KS_LD + 128*VT_LD + 64*PS_LD + 4*ST_LD) * 4)

__global__ __launch_bounds__(256, 1) void flash_tf32(
    const float* __restrict__ q,    // [B,H,S,256] tf32, scaled, kd-perm
    const float* __restrict__ kk,   // [B,H,S,256] tf32, kd-perm
    const float* __restrict__ vT,   // [B,2048,S]  tf32, s-perm
    float* __restrict__ ctx)        // [B,S,2048]
{
    extern __shared__ float sm[];
    float* qs   = sm;                        // 64 x 272
    float* ks   = qs + 64 * QS_LD;           // 64 x 272
    float* vs   = ks + 64 * KS_LD;           // 128 x 80
    float* ps   = vs + 128 * VT_LD;          // 64 x 80
    float* smax = ps + 64 * PS_LD;           // 2 x 72
    float* ssum = smax + 2 * ST_LD;          // 2 x 72

    const int tid  = threadIdx.x;
    const int warp = tid >> 5, lane = tid & 31;
    const int g    = lane >> 2;     // 0..7
    const int tg   = lane & 3;      // 0..3
    const int mrow = (warp & 3) * 16;   // warp row block
    const int ch   = warp >> 2;         // 0/1: S col-half & O d-half

    const int bh = blockIdx.y;
    const int b = bh >> 4, h = bh & 15;

    const float* vtb_base = vT + ((size_t)b * DMODEL + h * HDIM) * SEQ;

    for (int pass = 0; pass < 2; pass++) {
        const int qt = pass ? (31 - blockIdx.x) : blockIdx.x;

        // ---- issue q + k(0) as one group, v(0) as another ----
        const float* qbase = q + ((size_t)bh * SEQ + qt * 64) * QKDIM;
#pragma unroll
        for (int i = 0; i < 16; i++) {
            int c = tid + 256 * i;
            int r = c >> 6, c4 = (c & 63) * 4;
            cp_async16(qs + r * QS_LD + c4, qbase + (size_t)r * QKDIM + c4);
        }
        const float* kb0 = kk + ((size_t)bh * SEQ) * QKDIM;
#pragma unroll
        for (int i = 0; i < 16; i++) {
            int c = tid + 256 * i;
            int r = c >> 6, c4 = (c & 63) * 4;
            cp_async16(ks + r * KS_LD + c4, kb0 + (size_t)r * QKDIM + c4);
        }
        cp_commit();
#pragma unroll
        for (int i = 0; i < 8; i++) {
            int c = tid + 256 * i;
            int r = c >> 4, s4 = (c & 15) * 4;
            cp_async16(vs + r * VT_LD + s4, vtb_base + (size_t)r * SEQ + s4);
        }
        cp_commit();

        float m0 = -1e30f, m1 = -1e30f, l0 = 0.f, l1 = 0.f;
        float oacc[8][4];
#pragma unroll
        for (int nt = 0; nt < 8; nt++)
#pragma unroll
            for (int i = 0; i < 4; i++) oacc[nt][i] = 0.f;

        const int rg0 = qt * 64 + mrow + g;
        const int rg1 = rg0 + 8;

        for (int kt = 0; kt <= qt; kt++) {
            cp_wait1();
            __syncthreads();

            // ---- S = Q . K^T  (warp: 16 rows x its 32-col half) ----
            float sacc[4][4];
#pragma unroll
            for (int nt = 0; nt < 4; nt++)
#pragma unroll
                for (int i = 0; i < 4; i++) sacc[nt][i] = 0.f;

#pragma unroll
            for (int kb = 0; kb < 16; kb++) {
                float4 qa = *(const float4*)(qs + (mrow + g)     * QS_LD + kb * 16 + 4 * tg);
                float4 qb = *(const float4*)(qs + (mrow + g + 8) * QS_LD + kb * 16 + 4 * tg);
                uint32_t afA[4] = { __float_as_uint(qa.x), __float_as_uint(qb.x),
                                    __float_as_uint(qa.y), __float_as_uint(qb.y) };
                uint32_t afB[4] = { __float_as_uint(qa.z), __float_as_uint(qb.z),
                                    __float_as_uint(qa.w), __float_as_uint(qb.w) };
#pragma unroll
                for (int nt = 0; nt < 4; nt++) {
                    float4 kv = *(const float4*)(ks + (ch * 32 + 8 * nt + g) * KS_LD + kb * 16 + 4 * tg);
                    uint32_t bfA[2] = { __float_as_uint(kv.x), __float_as_uint(kv.y) };
                    uint32_t bfB[2] = { __float_as_uint(kv.z), __float_as_uint(kv.w) };
                    mma_tf32(sacc[nt], afA, bfA);
                    mma_tf32(sacc[nt], afB, bfB);
                }
            }

            // ---- causal mask (diagonal tile only) ----
            if (kt == qt) {
                int cb = kt * 64 + ch * 32 + 2 * tg;
#pragma unroll
                for (int nt = 0; nt < 4; nt++) {
                    int c0 = cb + 8 * nt, c1 = c0 + 1;
                    if (c0 > rg0) sacc[nt][0] = -1e30f;
                    if (c1 > rg0) sacc[nt][1] = -1e30f;
                    if (c0 > rg1) sacc[nt][2] = -1e30f;
                    if (c1 > rg1) sacc[nt][3] = -1e30f;
                }
            }

            // ---- own-half row max ----
            float tA = -1e30f, tB = -1e30f;
#pragma unroll
            for (int nt = 0; nt < 4; nt++) {
                tA = fmaxf(tA, fmaxf(sacc[nt][0], sacc[nt][1]));
                tB = fmaxf(tB, fmaxf(sacc[nt][2], sacc[nt][3]));
            }
            tA = fmaxf(tA, __shfl_xor_sync(0xffffffffu, tA, 1));
            tA = fmaxf(tA, __shfl_xor_sync(0xffffffffu, tA, 2));
            tB = fmaxf(tB, __shfl_xor_sync(0xffffffffu, tB, 1));
            tB = fmaxf(tB, __shfl_xor_sync(0xffffffffu, tB, 2));
            if (tg == 0) {
                smax[ch * ST_LD + mrow + g]     = tA;
                smax[ch * ST_LD + mrow + g + 8] = tB;
            }
            __syncthreads();

            // ---- combine max across halves; exp & partial sums ----
            float oAm = smax[(1 - ch) * ST_LD + mrow + g];
            float oBm = smax[(1 - ch) * ST_LD + mrow + g + 8];
            float mn0 = fmaxf(m0, fmaxf(tA, oAm));
            float mn1 = fmaxf(m1, fmaxf(tB, oBm));
            float f0 = __expf(m0 - mn0), f1 = __expf(m1 - mn1);
            m0 = mn0; m1 = mn1;

            float sum0 = 0.f, sum1 = 0.f;
            float* pr0 = ps + (mrow + g) * PS_LD;
            float* pr1 = ps + (mrow + g + 8) * PS_LD;
#pragma unroll
            for (int nt = 0; nt < 4; nt++) {
                int c0 = ch * 32 + 8 * nt + 2 * tg, c1 = c0 + 1;
                float p0 = __expf(sacc[nt][0] - mn0);
                float p1 = __expf(sacc[nt][1] - mn0);
                float p2 = __expf(sacc[nt][2] - mn1);
                float p3 = __expf(sacc[nt][3] - mn1);
                sum0 += p0 + p1;
                sum1 += p2 + p3;
                pr0[perm16(c0)] = f2tf32f(p0);
                pr0[perm16(c1)] = f2tf32f(p1);
                pr1[perm16(c0)] = f2tf32f(p2);
                pr1[perm16(c1)] = f2tf32f(p3);
            }
            sum0 += __shfl_xor_sync(0xffffffffu, sum0, 1);
            sum0 += __shfl_xor_sync(0xffffffffu, sum0, 2);
            sum1 += __shfl_xor_sync(0xffffffffu, sum1, 1);
            sum1 += __shfl_xor_sync(0xffffffffu, sum1, 2);
            if (tg == 0) {
                ssum[ch * ST_LD + mrow + g]     = sum0;
                ssum[ch * ST_LD + mrow + g + 8] = sum1;
            }
            __syncthreads();

            float oAs = ssum[(1 - ch) * ST_LD + mrow + g];
            float oBs = ssum[(1 - ch) * ST_LD + mrow + g + 8];
            l0 = l0 * f0 + sum0 + oAs;
            l1 = l1 * f1 + sum1 + oBs;

            // ---- prefetch k(kt+1) (overlaps P@V) ----
            if (kt < qt) {
                const float* kb = kk + ((size_t)bh * SEQ + (kt + 1) * 64) * QKDIM;
#pragma unroll
                for (int i = 0; i < 16; i++) {
                    int c = tid + 256 * i;
                    int r = c >> 6, c4 = (c & 63) * 4;
                    cp_async16(ks + r * KS_LD + c4, kb + (size_t)r * QKDIM + c4);
                }
            }
            cp_commit();

            cp_wait1();
            __syncthreads();

            // ---- rescale O, then O += P @ V  (warp: 16 rows x its 64 d-half) ----
#pragma unroll
            for (int nt = 0; nt < 8; nt++) {
                oacc[nt][0] *= f0; oacc[nt][1] *= f0;
                oacc[nt][2] *= f1; oacc[nt][3] *= f1;
            }
#pragma unroll
            for (int kb = 0; kb < 4; kb++) {
                float4 pa = *(const float4*)(ps + (mrow + g)     * PS_LD + kb * 16 + 4 * tg);
                float4 pb = *(const float4*)(ps + (mrow + g + 8) * PS_LD + kb * 16 + 4 * tg);
                uint32_t afA[4] = { __float_as_uint(pa.x), __float_as_uint(pb.x),
                                    __float_as_uint(pa.y), __float_as_uint(pb.y) };
                uint32_t afB[4] = { __float_as_uint(pa.z), __float_as_uint(pb.z),
                                    __float_as_uint(pa.w), __float_as_uint(pb.w) };
#pragma unroll
                for (int nt = 0; nt < 8; nt++) {
                    float4 vv = *(const float4*)(vs + (ch * 64 + 8 * nt + g) * VT_LD + kb * 16 + 4 * tg);
                    uint32_t bfA[2] = { __float_as_uint(vv.x), __float_as_uint(vv.y) };
                    uint32_t bfB[2] = { __float_as_uint(vv.z), __float_as_uint(vv.w) };
                    mma_tf32(oacc[nt], afA, bfA);
                    mma_tf32(oacc[nt], afB, bfB);
                }
            }

            __syncthreads();

            // ---- prefetch v(kt+1) (overlaps next S) ----
            if (kt < qt) {
                const float* vtb = vtb_base + (size_t)(kt + 1) * 64;
#pragma unroll
                for (int i = 0; i < 8; i++) {
                    int c = tid + 256 * i;
                    int r = c >> 4, s4 = (c & 15) * 4;
                    cp_async16(vs + r * VT_LD + s4, vtb + (size_t)r * SEQ + s4);
                }
            }
            cp_commit();
        }

        // ---- epilogue: warp writes its 16 rows x 64 d-half ----
        float inv0 = 1.f / l0, inv1 = 1.f / l1;
        float* o0 = ctx + ((size_t)b * SEQ + rg0) * DMODEL + h * HDIM + ch * 64 + 2 * tg;
        float* o1 = ctx + ((size_t)b * SEQ + rg1) * DMODEL + h * HDIM + ch * 64 + 2 * tg;
#pragma unroll
        for (int nt = 0; nt < 8; nt++) {
            *(float2*)(o0 + 8 * nt) = make_float2(oacc[nt][0] * inv0, oacc[nt][1] * inv0);
            *(float2*)(o1 + 8 * nt) = make_float2(oacc[nt][2] * inv1, oacc[nt][3] * inv1);
        }
    }
}

// ---------------------------------------------------------------------------
// Launch
// ---------------------------------------------------------------------------
extern "C" void kernel_launch(void* const* d_in, const int* in_sizes, int n_in,
                              void* d_out, int out_size)
{
    const float* h     = (const float*)d_in[0];
    const float* W_DKV = (const float*)d_in[1];
    const float* b_DKV = (const float*)d_in[2];
    const float* W_UK  = (const float*)d_in[3];
    const float* b_UK  = (const float*)d_in[4];
    const float* W_UV  = (const float*)d_in[5];
    const float* b_UV  = (const float*)d_in[6];
    const float* W_DQ  = (const float*)d_in[7];
    const float* b_DQ  = (const float*)d_in[8];
    const float* W_UQ  = (const float*)d_in[9];
    const float* b_UQ  = (const float*)d_in[10];
    const float* W_KR  = (const float*)d_in[11];
    const float* b_KR  = (const float*)d_in[12];
    const float* W_O   = (const float*)d_in[13];
    const float* b_O   = (const float*)d_in[14];

    float* out = (float*)d_out;
    float* cKV = out + OUT_SZ;
    float* kr  = cKV + CKV_SZ;

    float *p_cQ, *p_kC, *p_vT, *p_qC, *p_q, *p_k, *p_ctx;
    cudaGetSymbolAddress((void**)&p_cQ,  g_cQ);
    cudaGetSymbolAddress((void**)&p_kC,  g_kC);
    cudaGetSymbolAddress((void**)&p_vT,  g_vT);
    cudaGetSymbolAddress((void**)&p_qC,  g_qC);
    cudaGetSymbolAddress((void**)&p_q,   g_q);
    cudaGetSymbolAddress((void**)&p_k,   g_k);
    cudaGetSymbolAddress((void**)&p_ctx, g_ctx);

    cudaFuncSetAttribute(tf32_gemm_pipe,
                         cudaFuncAttributeMaxDynamicSharedMemorySize, GEMM_SMEM);
    cudaFuncSetAttribute(flash_tf32,
                         cudaFuncAttributeMaxDynamicSharedMemorySize, FL_SMEM);

    // projections
    tf32_gemm_pipe<<<dim3(DKV/128,    ROWS/128), 128, GEMM_SMEM>>>(ROWS, DKV,    DMODEL, h,    W_DKV, b_DKV, cKV, 0);
    tf32_gemm_pipe<<<dim3(DMODEL/128, ROWS/128), 128, GEMM_SMEM>>>(ROWS, DMODEL, DMODEL, h,    W_KR,  b_KR,  kr, 0);
    tf32_gemm_pipe<<<dim3(DQ/128,     ROWS/128), 128, GEMM_SMEM>>>(ROWS, DQ,     DMODEL, h,    W_DQ,  b_DQ,  p_cQ, 0);
    tf32_gemm_pipe<<<dim3(DMODEL/128, ROWS/128), 128, GEMM_SMEM>>>(ROWS, DMODEL, DKV,    cKV,  W_UK,  b_UK,  p_kC, 0);
    tf32_gemm_pipe<<<dim3(DMODEL/128, ROWS/128), 128, GEMM_SMEM>>>(ROWS, DMODEL, DKV,    cKV,  W_UV,  b_UV,  p_vT, 2);
    tf32_gemm_pipe<<<dim3(DMODEL/128, ROWS/128), 128, GEMM_SMEM>>>(ROWS, DMODEL, DQ,     p_cQ, W_UQ,  b_UQ,  p_qC, 0);

    // rope + repack (tf32, permuted)
    int pack_threads = BATCH * NHEADS * SEQ * 64;
    pack_q_kernel<<<pack_threads / 256, 256>>>(p_qC, p_q);
    pack_k_kernel<<<pack_threads / 256, 256>>>(p_kC, kr, p_k);

    // attention (8 warps/CTA)
    flash_tf32<<<dim3(16, BATCH*NHEADS), 256, FL_SMEM>>>(p_q, p_k, p_vT, p_ctx);

    // output projection
    tf32_gemm_pipe<<<dim3(DMODEL/128, ROWS/128), 128, GEMM_SMEM>>>(ROWS, DMODEL, DMODEL, p_ctx, W_O, b_O, out, 0);
}

// round 9
// speedup vs baseline: 1.2700x; 1.2363x over previous
#include <cuda_runtime.h>
#include <cuda_fp16.h>
#include <math.h>
#include <stdint.h>
#include <string.h>

// ---------------------------------------------------------------------------
// Problem constants
// ---------------------------------------------------------------------------
#define BATCH    2
#define SEQ      2048
#define DMODEL   2048
#define DKV      512
#define DQ       1536
#define NHEADS   16
#define HDIM     128
#define ROWS     (BATCH*SEQ)            // 4096
#define QKDIM    256
#define SCALE    0.0625f                // 1/sqrt(256)

#define OUT_SZ   (BATCH*SEQ*DMODEL)
#define CKV_SZ   (BATCH*SEQ*DKV)

// ---------------------------------------------------------------------------
// Scratch
// ---------------------------------------------------------------------------
__device__ float  g_cQ [ROWS*DQ];
__device__ float  g_kC [ROWS*DMODEL];
__device__ __half g_vT [(size_t)BATCH*DMODEL*SEQ]; // V^T fp16, s-permuted
__device__ float  g_qC [ROWS*DMODEL];
__device__ __half g_q  [(size_t)BATCH*NHEADS*SEQ*QKDIM]; // fp16, scaled, perm
__device__ __half g_k  [(size_t)BATCH*NHEADS*SEQ*QKDIM]; // fp16, perm
__device__ float  g_ctx[ROWS*DMODEL];

// fragment-order permutation within 32-element blocks of the reduction dim:
// lane tg owns k = {2tg,2tg+1, +8, +16, +24} -> contiguous 8 halves at 8*tg
__device__ __forceinline__ int perm32(int k) {
    return (k & ~31) | (((k & 7) >> 1) << 3) | (((k >> 3) & 3) << 1) | (k & 1);
}

// ---------------------------------------------------------------------------
// helpers
// ---------------------------------------------------------------------------
__device__ __forceinline__ uint32_t f2tf32(float x) {
    uint32_t r;
    asm("cvt.rna.tf32.f32 %0, %1;" : "=r"(r) : "f"(x));
    return r;
}
__device__ __forceinline__ float f2tf32f(float x) {
    return __uint_as_float(f2tf32(x));
}

__device__ __forceinline__ uint32_t h2_as_u32(__half2 h) {
    uint32_t u;
    memcpy(&u, &h, 4);
    return u;
}

__device__ __forceinline__ void mma_tf32(float c[4],
                                         const uint32_t a[4],
                                         const uint32_t b[2]) {
    asm volatile(
        "mma.sync.aligned.m16n8k8.row.col.f32.tf32.tf32.f32 "
        "{%0,%1,%2,%3}, {%4,%5,%6,%7}, {%8,%9}, {%0,%1,%2,%3};\n"
        : "+f"(c[0]), "+f"(c[1]), "+f"(c[2]), "+f"(c[3])
        : "r"(a[0]), "r"(a[1]), "r"(a[2]), "r"(a[3]),
          "r"(b[0]), "r"(b[1]));
}

__device__ __forceinline__ void mma_f16(float c[4],
                                        uint32_t a0, uint32_t a1,
                                        uint32_t a2, uint32_t a3,
                                        uint32_t b0, uint32_t b1) {
    asm volatile(
        "mma.sync.aligned.m16n8k16.row.col.f32.f16.f16.f32 "
        "{%0,%1,%2,%3}, {%4,%5,%6,%7}, {%8,%9}, {%0,%1,%2,%3};\n"
        : "+f"(c[0]), "+f"(c[1]), "+f"(c[2]), "+f"(c[3])
        : "r"(a0), "r"(a1), "r"(a2), "r"(a3), "r"(b0), "r"(b1));
}

__device__ __forceinline__ void cp_async16(void* smem_dst, const void* gsrc) {
    uint32_t sa = (uint32_t)__cvta_generic_to_shared(smem_dst);
    asm volatile("cp.async.cg.shared.global [%0], [%1], 16;\n"
                 :: "r"(sa), "l"(gsrc));
}
__device__ __forceinline__ void cp_commit() {
    asm volatile("cp.async.commit_group;\n" ::: "memory");
}
__device__ __forceinline__ void cp_wait1() {
    asm volatile("cp.async.wait_group 1;\n" ::: "memory");
}
__device__ __forceinline__ void cp_wait2() {
    asm volatile("cp.async.wait_group 2;\n" ::: "memory");
}

// ---------------------------------------------------------------------------
// Pipelined TF32 GEMM.  mode: 0 = plain fp32 store,
//                             2 = fp16 store transposed + s-perm into vT
// ---------------------------------------------------------------------------
#define GSTAGES 3
#define GBK     32
#define A_LD    36
#define B_LD    136
#define STAGE_FLOATS (128*A_LD + GBK*B_LD)
#define GEMM_SMEM    (GSTAGES*STAGE_FLOATS*4)

__device__ __forceinline__ void g_load_stage(
    float* As, float* Bs,
    const float* __restrict__ Ab, const float* __restrict__ Bb,
    int k0, int K, int N, int tid)
{
#pragma unroll
    for (int i = 0; i < 8; i++) {
        int c = tid + 128 * i;
        int am = c >> 3, ak = (c & 7) * 4;
        cp_async16(As + am * A_LD + ak, Ab + (size_t)am * K + k0 + ak);
    }
#pragma unroll
    for (int i = 0; i < 8; i++) {
        int c = tid + 128 * i;
        int bk = c >> 5, bn = (c & 31) * 4;
        cp_async16(Bs + bk * B_LD + bn, Bb + (size_t)(k0 + bk) * N + bn);
    }
}

__global__ __launch_bounds__(128, 2) void tf32_gemm_pipe(
    int M, int N, int K,
    const float* __restrict__ A, const float* __restrict__ B,
    const float* __restrict__ bias, float* __restrict__ C, int mode)
{
    extern __shared__ float gsm[];

    const int tid  = threadIdx.x;
    const int bx   = blockIdx.x, by = blockIdx.y;
    const int warp = tid >> 5, lane = tid & 31;
    const int wm   = (warp >> 1) * 64;
    const int wn   = (warp & 1) * 64;
    const int g    = lane >> 2;
    const int tg   = lane & 3;

    const float* Ab = A + (size_t)(by * 128) * K;
    const float* Bb = B + bx * 128;

    float acc[4][8][4];
#pragma unroll
    for (int mt = 0; mt < 4; mt++)
#pragma unroll
        for (int nt = 0; nt < 8; nt++)
#pragma unroll
            for (int i = 0; i < 4; i++) acc[mt][nt][i] = 0.f;

#pragma unroll
    for (int s = 0; s < GSTAGES; s++) {
        if (s * GBK < K)
            g_load_stage(gsm + s * STAGE_FLOATS,
                         gsm + s * STAGE_FLOATS + 128 * A_LD,
                         Ab, Bb, s * GBK, K, N, tid);
        cp_commit();
    }

    int rs = 0;
    for (int k0 = 0; k0 < K; k0 += GBK) {
        cp_wait2();
        __syncthreads();

        float* As = gsm + rs * STAGE_FLOATS;
        float* Bs = As + 128 * A_LD;

#pragma unroll
        for (int ks = 0; ks < GBK; ks += 8) {
            uint32_t af[4][4], bf[8][2];
#pragma unroll
            for (int mt = 0; mt < 4; mt++) {
                const float* ab = As + (wm + mt * 16 + g) * A_LD + ks + tg;
                af[mt][0] = f2tf32(ab[0]);
                af[mt][2] = f2tf32(ab[4]);
                af[mt][1] = f2tf32(ab[8 * A_LD]);
                af[mt][3] = f2tf32(ab[8 * A_LD + 4]);
            }
#pragma unroll
            for (int nt = 0; nt < 8; nt++) {
                int n0 = wn + nt * 8;
                bf[nt][0] = f2tf32(Bs[(ks + tg) * B_LD + n0 + g]);
                bf[nt][1] = f2tf32(Bs[(ks + tg + 4) * B_LD + n0 + g]);
            }
#pragma unroll
            for (int mt = 0; mt < 4; mt++)
#pragma unroll
                for (int nt = 0; nt < 8; nt++)
                    mma_tf32(acc[mt][nt], af[mt], bf[nt]);
        }

        __syncthreads();
        int kl = k0 + GSTAGES * GBK;
        if (kl < K)
            g_load_stage(As, Bs, Ab, Bb, kl, K, N, tid);
        cp_commit();
        rs = rs + 1; if (rs == GSTAGES) rs = 0;
    }

#pragma unroll
    for (int mt = 0; mt < 4; mt++) {
        int r_lo = by * 128 + wm + mt * 16 + g;
        int r_hi = r_lo + 8;
#pragma unroll
        for (int nt = 0; nt < 8; nt++) {
            int col = bx * 128 + wn + nt * 8 + 2 * tg;
            float b0 = bias[col], b1 = bias[col + 1];
            float v00 = acc[mt][nt][0] + b0, v01 = acc[mt][nt][1] + b1;
            float v10 = acc[mt][nt][2] + b0, v11 = acc[mt][nt][3] + b1;
            if (mode == 2) {
                __half* Ch = (__half*)C;
                int blo = r_lo >> 11, slo = perm32(r_lo & 2047);
                int bhi = r_hi >> 11, shi = perm32(r_hi & 2047);
                Ch[((size_t)blo * N + col)     * SEQ + slo] = __float2half(v00);
                Ch[((size_t)blo * N + col + 1) * SEQ + slo] = __float2half(v01);
                Ch[((size_t)bhi * N + col)     * SEQ + shi] = __float2half(v10);
                Ch[((size_t)bhi * N + col + 1) * SEQ + shi] = __float2half(v11);
            } else {
                *(float2*)(&C[(size_t)r_lo * N + col]) = make_float2(v00, v01);
                *(float2*)(&C[(size_t)r_hi * N + col]) = make_float2(v10, v11);
            }
        }
    }
}

// ---------------------------------------------------------------------------
// Pack q (fp16, scaled, perm32 on k-dim)
// ---------------------------------------------------------------------------
__global__ __launch_bounds__(256) void pack_q_kernel(
    const float* __restrict__ qC, __half* __restrict__ q)
{
    int gid = blockIdx.x * blockDim.x + threadIdx.x;
    int i = gid & 63;
    int s = (gid >> 6) & (SEQ - 1);
    int h = (gid >> 17) & (NHEADS - 1);
    int b = gid >> 21;

    const float* src = qC + ((size_t)(b * SEQ + s)) * DMODEL + h * HDIM;
    float x1 = src[2 * i], x2 = src[2 * i + 1];

    float inv = powf(10000.0f, -(float)(2 * i) / 128.0f);
    float ang = (float)s * inv;
    float sn, cs; sincosf(ang, &sn, &cs);

    __half* dst = q + (((size_t)(b * NHEADS + h)) * SEQ + s) * QKDIM;
    dst[perm32(2 * i)]       = __float2half(x1 * SCALE);
    dst[perm32(2 * i + 1)]   = __float2half(x2 * SCALE);
    dst[perm32(128 + 2 * i)] = __float2half((x1 * cs - x2 * sn) * SCALE);
    dst[perm32(129 + 2 * i)] = __float2half((x1 * sn + x2 * cs) * SCALE);
}

// ---------------------------------------------------------------------------
// Pack k (fp16, perm32 on k-dim)
// ---------------------------------------------------------------------------
__global__ __launch_bounds__(256) void pack_k_kernel(
    const float* __restrict__ kC, const float* __restrict__ kr,
    __half* __restrict__ k)
{
    int gid = blockIdx.x * blockDim.x + threadIdx.x;
    int i = gid & 63;
    int s = (gid >> 6) & (SEQ - 1);
    int h = (gid >> 17) & (NHEADS - 1);
    int b = gid >> 21;

    size_t soff = ((size_t)(b * SEQ + s)) * DMODEL + h * HDIM;
    const float* raw = kC + soff;
    const float* rot = kr + soff;
    float x1 = rot[2 * i], x2 = rot[2 * i + 1];

    float inv = powf(10000.0f, -(float)(2 * i) / 128.0f);
    float ang = (float)s * inv;
    float sn, cs; sincosf(ang, &sn, &cs);

    __half* dst = k + (((size_t)(b * NHEADS + h)) * SEQ + s) * QKDIM;
    dst[perm32(2 * i)]       = __float2half(raw[2 * i]);
    dst[perm32(2 * i + 1)]   = __float2half(raw[2 * i + 1]);
    dst[perm32(128 + 2 * i)] = __float2half(x1 * cs - x2 * sn);
    dst[perm32(129 + 2 * i)] = __float2half(x1 * sn + x2 * cs);
}

// ---------------------------------------------------------------------------
// FP16 flash attention.  BM=BN=64, 128 threads (4 warps over M, each warp
// owns 16 rows x all 64 cols).  Q in registers for whole loop; P stays in
// registers (S-output frag == PV A-frag).  2 CTAs/SM.
// ---------------------------------------------------------------------------
#define K_LDH 288        // halves per k row   (576B = 144 words == 16 mod 32)
#define V_LDH 96         // halves per vT row  (192B =  48 words == 16 mod 32)
#define FL_SMEM ((64*K_LDH + 128*V_LDH) * 2)   // 61440 bytes

__global__ __launch_bounds__(128, 2) void flash_f16(
    const __half* __restrict__ q,    // [B,H,S,256] fp16, scaled, perm
    const __half* __restrict__ kk,   // [B,H,S,256] fp16, perm
    const __half* __restrict__ vT,   // [B,2048d,2048s] fp16, s-perm
    float* __restrict__ ctx)         // [B,S,2048]
{
    extern __shared__ __half smh[];
    __half* ks = smh;                 // 64 x 288
    __half* vs = ks + 64 * K_LDH;     // 128 x 96

    const int tid  = threadIdx.x;
    const int warp = tid >> 5, lane = tid & 31;
    const int g    = lane >> 2;      // 0..7
    const int tg   = lane & 3;       // 0..3
    const int wm   = warp * 16;

    const int qt = 31 - blockIdx.x;  // big tiles scheduled first
    const int bh = blockIdx.y;
    const int b = bh >> 4, h = bh & 15;

    const __half* vtb_base = vT + ((size_t)b * DMODEL + h * HDIM) * SEQ;
    const __half* kbh      = kk + ((size_t)bh * SEQ) * QKDIM;

    // ---- load Q fragments straight into registers (rows wm+g, wm+g+8) ----
    const int rg0 = qt * 64 + wm + g;
    const int rg1 = rg0 + 8;
    uint4 qlo[8], qhi[8];
    {
        const uint4* q0 = (const uint4*)(q + ((size_t)bh * SEQ + rg0) * QKDIM) + tg;
        const uint4* q1 = (const uint4*)(q + ((size_t)bh * SEQ + rg1) * QKDIM) + tg;
#pragma unroll
        for (int kb = 0; kb < 8; kb++) {
            qlo[kb] = q0[kb * 4];
            qhi[kb] = q1[kb * 4];
        }
    }

    // ---- issue k(0) group, then v(0) group ----
#pragma unroll
    for (int i = 0; i < 16; i++) {
        int c = tid + 128 * i;               // 0..2047 chunks of 16B
        int r = c >> 5, off = (c & 31) * 8;  // halves
        cp_async16(ks + r * K_LDH + off, kbh + (size_t)r * QKDIM + off);
    }
    cp_commit();
#pragma unroll
    for (int i = 0; i < 8; i++) {
        int c = tid + 128 * i;               // 0..1023 chunks
        int r = c >> 3, off = (c & 7) * 8;
        cp_async16(vs + r * V_LDH + off, vtb_base + (size_t)r * SEQ + off);
    }
    cp_commit();

    float m0 = -1e30f, m1 = -1e30f, l0 = 0.f, l1 = 0.f;
    float oacc[16][4];
#pragma unroll
    for (int nt = 0; nt < 16; nt++)
#pragma unroll
        for (int i = 0; i < 4; i++) oacc[nt][i] = 0.f;

    for (int kt = 0; kt <= qt; kt++) {
        cp_wait1();               // k(kt) ready (v(kt) may be in flight)
        __syncthreads();

        // ---- S = Q . K^T : 16 rows x 64 cols per warp ----
        float sacc[8][4];
#pragma unroll
        for (int nt = 0; nt < 8; nt++)
#pragma unroll
            for (int i = 0; i < 4; i++) sacc[nt][i] = 0.f;

#pragma unroll
        for (int kb = 0; kb < 8; kb++) {          // k32 blocks
            uint4 L = qlo[kb], H = qhi[kb];
#pragma unroll
            for (int nt = 0; nt < 8; nt++) {
                uint4 kv = *(const uint4*)(ks + (8 * nt + g) * K_LDH + kb * 32 + 8 * tg);
                mma_f16(sacc[nt], L.x, H.x, L.y, H.y, kv.x, kv.y);
                mma_f16(sacc[nt], L.z, H.z, L.w, H.w, kv.z, kv.w);
            }
        }

        // ---- causal mask (diagonal tile only) ----
        if (kt == qt) {
            int cb = kt * 64 + 2 * tg;
#pragma unroll
            for (int nt = 0; nt < 8; nt++) {
                int c0 = cb + 8 * nt, c1 = c0 + 1;
                if (c0 > rg0) sacc[nt][0] = -1e30f;
                if (c1 > rg0) sacc[nt][1] = -1e30f;
                if (c0 > rg1) sacc[nt][2] = -1e30f;
                if (c1 > rg1) sacc[nt][3] = -1e30f;
            }
        }

        // ---- online softmax (warp-local rows) ----
        float tA = -1e30f, tB = -1e30f;
#pragma unroll
        for (int nt = 0; nt < 8; nt++) {
            tA = fmaxf(tA, fmaxf(sacc[nt][0], sacc[nt][1]));
            tB = fmaxf(tB, fmaxf(sacc[nt][2], sacc[nt][3]));
        }
        tA = fmaxf(tA, __shfl_xor_sync(0xffffffffu, tA, 1));
        tA = fmaxf(tA, __shfl_xor_sync(0xffffffffu, tA, 2));
        tB = fmaxf(tB, __shfl_xor_sync(0xffffffffu, tB, 1));
        tB = fmaxf(tB, __shfl_xor_sync(0xffffffffu, tB, 2));

        float mn0 = fmaxf(m0, tA), mn1 = fmaxf(m1, tB);
        float f0 = __expf(m0 - mn0), f1 = __expf(m1 - mn1);
        m0 = mn0; m1 = mn1;

        float sum0 = 0.f, sum1 = 0.f;
        uint32_t ph01[8], ph23[8];   // P as half2: cols (2tg,2tg+1) per nt
#pragma unroll
        for (int nt = 0; nt < 8; nt++) {
            float p0 = __expf(sacc[nt][0] - mn0);
            float p1 = __expf(sacc[nt][1] - mn0);
            float p2 = __expf(sacc[nt][2] - mn1);
            float p3 = __expf(sacc[nt][3] - mn1);
            sum0 += p0 + p1;
            sum1 += p2 + p3;
            ph01[nt] = h2_as_u32(__floats2half2_rn(p0, p1));
            ph23[nt] = h2_as_u32(__floats2half2_rn(p2, p3));
        }
        sum0 += __shfl_xor_sync(0xffffffffu, sum0, 1);
        sum0 += __shfl_xor_sync(0xffffffffu, sum0, 2);
        sum1 += __shfl_xor_sync(0xffffffffu, sum1, 1);
        sum1 += __shfl_xor_sync(0xffffffffu, sum1, 2);
        l0 = l0 * f0 + sum0;
        l1 = l1 * f1 + sum1;

        __syncthreads();          // all warps done reading ks

        // ---- prefetch k(kt+1) (overlaps P@V) ----
        if (kt < qt) {
            const __half* kb = kbh + (size_t)(kt + 1) * 64 * QKDIM;
#pragma unroll
            for (int i = 0; i < 16; i++) {
                int c = tid + 128 * i;
                int r = c >> 5, off = (c & 31) * 8;
                cp_async16(ks + r * K_LDH + off, kb + (size_t)r * QKDIM + off);
            }
        }
        cp_commit();

        cp_wait1();               // v(kt) ready (k(kt+1) in flight)
        __syncthreads();

        // ---- rescale O, then O += P @ V (P from registers) ----
#pragma unroll
        for (int nt = 0; nt < 16; nt++) {
            oacc[nt][0] *= f0; oacc[nt][1] *= f0;
            oacc[nt][2] *= f1; oacc[nt][3] *= f1;
        }
#pragma unroll
        for (int kb = 0; kb < 2; kb++) {          // s32 blocks
            uint32_t aL0 = ph01[4 * kb + 0], aL1 = ph23[4 * kb + 0];
            uint32_t aL2 = ph01[4 * kb + 1], aL3 = ph23[4 * kb + 1];
            uint32_t aH0 = ph01[4 * kb + 2], aH1 = ph23[4 * kb + 2];
            uint32_t aH2 = ph01[4 * kb + 3], aH3 = ph23[4 * kb + 3];
#pragma unroll
            for (int nt = 0; nt < 16; nt++) {
                uint4 vv = *(const uint4*)(vs + (8 * nt + g) * V_LDH + kb * 32 + 8 * tg);
                mma_f16(oacc[nt], aL0, aL1, aL2, aL3, vv.x, vv.y);
                mma_f16(oacc[nt], aH0, aH1, aH2, aH3, vv.z, vv.w);
            }
        }

        __syncthreads();          // all warps done reading vs

        // ---- prefetch v(kt+1) (overlaps next S) ----
        if (kt < qt) {
            const __half* vtb = vtb_base + (size_t)(kt + 1) * 64;
#pragma unroll
            for (int i = 0; i < 8; i++) {
                int c = tid + 128 * i;
                int r = c >> 3, off = (c & 7) * 8;
                cp_async16(vs + r * V_LDH + off, vtb + (size_t)r * SEQ + off);
            }
        }
        cp_commit();
    }

    // ---- epilogue ----
    float inv0 = 1.f / l0, inv1 = 1.f / l1;
    float* o0 = ctx + ((size_t)b * SEQ + rg0) * DMODEL + h * HDIM + 2 * tg;
    float* o1 = ctx + ((size_t)b * SEQ + rg1) * DMODEL + h * HDIM + 2 * tg;
#pragma unroll
    for (int nt = 0; nt < 16; nt++) {
        *(float2*)(o0 + 8 * nt) = make_float2(oacc[nt][0] * inv0, oacc[nt][1] * inv0);
        *(float2*)(o1 + 8 * nt) = make_float2(oacc[nt][2] * inv1, oacc[nt][3] * inv1);
    }
}

// ---------------------------------------------------------------------------
// Launch
// ---------------------------------------------------------------------------
extern "C" void kernel_launch(void* const* d_in, const int* in_sizes, int n_in,
                              void* d_out, int out_size)
{
    const float* h     = (const float*)d_in[0];
    const float* W_DKV = (const float*)d_in[1];
    const float* b_DKV = (const float*)d_in[2];
    const float* W_UK  = (const float*)d_in[3];
    const float* b_UK  = (const float*)d_in[4];
    const float* W_UV  = (const float*)d_in[5];
    const float* b_UV  = (const float*)d_in[6];
    const float* W_DQ  = (const float*)d_in[7];
    const float* b_DQ  = (const float*)d_in[8];
    const float* W_UQ  = (const float*)d_in[9];
    const float* b_UQ  = (const float*)d_in[10];
    const float* W_KR  = (const float*)d_in[11];
    const float* b_KR  = (const float*)d_in[12];
    const float* W_O   = (const float*)d_in[13];
    const float* b_O   = (const float*)d_in[14];

    float* out = (float*)d_out;
    float* cKV = out + OUT_SZ;
    float* kr  = cKV + CKV_SZ;

    float *p_cQ, *p_kC, *p_qC, *p_ctx;
    __half *p_vT, *p_q, *p_k;
    cudaGetSymbolAddress((void**)&p_cQ,  g_cQ);
    cudaGetSymbolAddress((void**)&p_kC,  g_kC);
    cudaGetSymbolAddress((void**)&p_vT,  g_vT);
    cudaGetSymbolAddress((void**)&p_qC,  g_qC);
    cudaGetSymbolAddress((void**)&p_q,   g_q);
    cudaGetSymbolAddress((void**)&p_k,   g_k);
    cudaGetSymbolAddress((void**)&p_ctx, g_ctx);

    cudaFuncSetAttribute(tf32_gemm_pipe,
                         cudaFuncAttributeMaxDynamicSharedMemorySize, GEMM_SMEM);
    cudaFuncSetAttribute(flash_f16,
                         cudaFuncAttributeMaxDynamicSharedMemorySize, FL_SMEM);

    // projections (tf32)
    tf32_gemm_pipe<<<dim3(DKV/128,    ROWS/128), 128, GEMM_SMEM>>>(ROWS, DKV,    DMODEL, h,    W_DKV, b_DKV, cKV, 0);
    tf32_gemm_pipe<<<dim3(DMODEL/128, ROWS/128), 128, GEMM_SMEM>>>(ROWS, DMODEL, DMODEL, h,    W_KR,  b_KR,  kr, 0);
    tf32_gemm_pipe<<<dim3(DQ/128,     ROWS/128), 128, GEMM_SMEM>>>(ROWS, DQ,     DMODEL, h,    W_DQ,  b_DQ,  p_cQ, 0);
    tf32_gemm_pipe<<<dim3(DMODEL/128, ROWS/128), 128, GEMM_SMEM>>>(ROWS, DMODEL, DKV,    cKV,  W_UK,  b_UK,  p_kC, 0);
    tf32_gemm_pipe<<<dim3(DMODEL/128, ROWS/128), 128, GEMM_SMEM>>>(ROWS, DMODEL, DKV,    cKV,  W_UV,  b_UV,  (float*)p_vT, 2);
    tf32_gemm_pipe<<<dim3(DMODEL/128, ROWS/128), 128, GEMM_SMEM>>>(ROWS, DMODEL, DQ,     p_cQ, W_UQ,  b_UQ,  p_qC, 0);

    // rope + repack (fp16, permuted)
    int pack_threads = BATCH * NHEADS * SEQ * 64;
    pack_q_kernel<<<pack_threads / 256, 256>>>(p_qC, p_q);
    pack_k_kernel<<<pack_threads / 256, 256>>>(p_kC, kr, p_k);

    // attention (fp16 tensor cores, register P)
    flash_f16<<<dim3(32, BATCH*NHEADS), 128, FL_SMEM>>>(p_q, p_k, p_vT, p_ctx);

    // output projection
    tf32_gemm_pipe<<<dim3(DMODEL/128, ROWS/128), 128, GEMM_SMEM>>>(ROWS, DMODEL, DMODEL, p_ctx, W_O, b_O, out, 0);
}

// round 10
// speedup vs baseline: 1.2789x; 1.0070x over previous
#include <cuda_runtime.h>
#include <cuda_fp16.h>
#include <math.h>
#include <stdint.h>
#include <string.h>

// ---------------------------------------------------------------------------
// Problem constants
// ---------------------------------------------------------------------------
#define BATCH    2
#define SEQ      2048
#define DMODEL   2048
#define DKV      512
#define DQ       1536
#define NHEADS   16
#define HDIM     128
#define ROWS     (BATCH*SEQ)            // 4096
#define QKDIM    256
#define SCALE    0.0625f                // 1/sqrt(256)

#define OUT_SZ   (BATCH*SEQ*DMODEL)
#define CKV_SZ   (BATCH*SEQ*DKV)

// ---------------------------------------------------------------------------
// Scratch
// ---------------------------------------------------------------------------
__device__ float  g_cQ [ROWS*DQ];
__device__ float  g_kC [ROWS*DMODEL];
__device__ __half g_vT [(size_t)BATCH*DMODEL*SEQ]; // V^T fp16, s-permuted
__device__ float  g_qC [ROWS*DMODEL];
__device__ __half g_q  [(size_t)BATCH*NHEADS*SEQ*QKDIM]; // fp16, scaled, perm
__device__ __half g_k  [(size_t)BATCH*NHEADS*SEQ*QKDIM]; // fp16, perm
__device__ float  g_ctx[ROWS*DMODEL];
__device__ float2 g_rope[SEQ*64];                  // (cos,sin) per (s,i)

// fragment-order permutation within 32-element blocks of the reduction dim:
// lane tg owns k = {2tg,2tg+1, +8, +16, +24} -> contiguous 8 halves at 8*tg
__device__ __forceinline__ int perm32(int k) {
    return (k & ~31) | (((k & 7) >> 1) << 3) | (((k >> 3) & 3) << 1) | (k & 1);
}

// ---------------------------------------------------------------------------
// helpers
// ---------------------------------------------------------------------------
__device__ __forceinline__ uint32_t f2tf32(float x) {
    uint32_t r;
    asm("cvt.rna.tf32.f32 %0, %1;" : "=r"(r) : "f"(x));
    return r;
}
__device__ __forceinline__ float f2tf32f(float x) {
    return __uint_as_float(f2tf32(x));
}

__device__ __forceinline__ uint32_t h2_as_u32(__half2 h) {
    uint32_t u;
    memcpy(&u, &h, 4);
    return u;
}

__device__ __forceinline__ void mma_tf32(float c[4],
                                         const uint32_t a[4],
                                         const uint32_t b[2]) {
    asm volatile(
        "mma.sync.aligned.m16n8k8.row.col.f32.tf32.tf32.f32 "
        "{%0,%1,%2,%3}, {%4,%5,%6,%7}, {%8,%9}, {%0,%1,%2,%3};\n"
        : "+f"(c[0]), "+f"(c[1]), "+f"(c[2]), "+f"(c[3])
        : "r"(a[0]), "r"(a[1]), "r"(a[2]), "r"(a[3]),
          "r"(b[0]), "r"(b[1]));
}

__device__ __forceinline__ void mma_f16(float c[4],
                                        uint32_t a0, uint32_t a1,
                                        uint32_t a2, uint32_t a3,
                                        uint32_t b0, uint32_t b1) {
    asm volatile(
        "mma.sync.aligned.m16n8k16.row.col.f32.f16.f16.f32 "
        "{%0,%1,%2,%3}, {%4,%5,%6,%7}, {%8,%9}, {%0,%1,%2,%3};\n"
        : "+f"(c[0]), "+f"(c[1]), "+f"(c[2]), "+f"(c[3])
        : "r"(a0), "r"(a1), "r"(a2), "r"(a3), "r"(b0), "r"(b1));
}

__device__ __forceinline__ void cp_async16(void* smem_dst, const void* gsrc) {
    uint32_t sa = (uint32_t)__cvta_generic_to_shared(smem_dst);
    asm volatile("cp.async.cg.shared.global [%0], [%1], 16;\n"
                 :: "r"(sa), "l"(gsrc));
}
__device__ __forceinline__ void cp_commit() {
    asm volatile("cp.async.commit_group;\n" ::: "memory");
}
__device__ __forceinline__ void cp_wait1() {
    asm volatile("cp.async.wait_group 1;\n" ::: "memory");
}
__device__ __forceinline__ void cp_wait2() {
    asm volatile("cp.async.wait_group 2;\n" ::: "memory");
}

// ---------------------------------------------------------------------------
// Rope table: cos/sin per (s, i) — hoists powf/sincosf out of the packs.
// Identical math to the previous in-pack computation (bit-identical numerics).
// ---------------------------------------------------------------------------
__global__ __launch_bounds__(256) void rope_table_kernel(float2* __restrict__ t)
{
    int idx = blockIdx.x * 256 + threadIdx.x;     // 0 .. SEQ*64-1
    int i = idx & 63;
    int s = idx >> 6;
    float inv = powf(10000.0f, -(float)(2 * i) / 128.0f);
    float sn, cs; sincosf((float)s * inv, &sn, &cs);
    t[idx] = make_float2(cs, sn);
}

// ---------------------------------------------------------------------------
// Pipelined TF32 GEMM.  mode: 0 = plain fp32 store,
//                             2 = fp16 store transposed + s-perm into vT
// ---------------------------------------------------------------------------
#define GSTAGES 3
#define GBK     32
#define A_LD    36
#define B_LD    136
#define STAGE_FLOATS (128*A_LD + GBK*B_LD)
#define GEMM_SMEM    (GSTAGES*STAGE_FLOATS*4)

__device__ __forceinline__ void g_load_stage(
    float* As, float* Bs,
    const float* __restrict__ Ab, const float* __restrict__ Bb,
    int k0, int K, int N, int tid)
{
#pragma unroll
    for (int i = 0; i < 8; i++) {
        int c = tid + 128 * i;
        int am = c >> 3, ak = (c & 7) * 4;
        cp_async16(As + am * A_LD + ak, Ab + (size_t)am * K + k0 + ak);
    }
#pragma unroll
    for (int i = 0; i < 8; i++) {
        int c = tid + 128 * i;
        int bk = c >> 5, bn = (c & 31) * 4;
        cp_async16(Bs + bk * B_LD + bn, Bb + (size_t)(k0 + bk) * N + bn);
    }
}

__global__ __launch_bounds__(128, 2) void tf32_gemm_pipe(
    int M, int N, int K,
    const float* __restrict__ A, const float* __restrict__ B,
    const float* __restrict__ bias, float* __restrict__ C, int mode)
{
    extern __shared__ float gsm[];

    const int tid  = threadIdx.x;
    const int bx   = blockIdx.x, by = blockIdx.y;
    const int warp = tid >> 5, lane = tid & 31;
    const int wm   = (warp >> 1) * 64;
    const int wn   = (warp & 1) * 64;
    const int g    = lane >> 2;
    const int tg   = lane & 3;

    const float* Ab = A + (size_t)(by * 128) * K;
    const float* Bb = B + bx * 128;

    float acc[4][8][4];
#pragma unroll
    for (int mt = 0; mt < 4; mt++)
#pragma unroll
        for (int nt = 0; nt < 8; nt++)
#pragma unroll
            for (int i = 0; i < 4; i++) acc[mt][nt][i] = 0.f;

#pragma unroll
    for (int s = 0; s < GSTAGES; s++) {
        if (s * GBK < K)
            g_load_stage(gsm + s * STAGE_FLOATS,
                         gsm + s * STAGE_FLOATS + 128 * A_LD,
                         Ab, Bb, s * GBK, K, N, tid);
        cp_commit();
    }

    int rs = 0;
    for (int k0 = 0; k0 < K; k0 += GBK) {
        cp_wait2();
        __syncthreads();

        float* As = gsm + rs * STAGE_FLOATS;
        float* Bs = As + 128 * A_LD;

#pragma unroll
        for (int ks = 0; ks < GBK; ks += 8) {
            uint32_t af[4][4], bf[8][2];
#pragma unroll
            for (int mt = 0; mt < 4; mt++) {
                const float* ab = As + (wm + mt * 16 + g) * A_LD + ks + tg;
                af[mt][0] = f2tf32(ab[0]);
                af[mt][2] = f2tf32(ab[4]);
                af[mt][1] = f2tf32(ab[8 * A_LD]);
                af[mt][3] = f2tf32(ab[8 * A_LD + 4]);
            }
#pragma unroll
            for (int nt = 0; nt < 8; nt++) {
                int n0 = wn + nt * 8;
                bf[nt][0] = f2tf32(Bs[(ks + tg) * B_LD + n0 + g]);
                bf[nt][1] = f2tf32(Bs[(ks + tg + 4) * B_LD + n0 + g]);
            }
#pragma unroll
            for (int mt = 0; mt < 4; mt++)
#pragma unroll
                for (int nt = 0; nt < 8; nt++)
                    mma_tf32(acc[mt][nt], af[mt], bf[nt]);
        }

        __syncthreads();
        int kl = k0 + GSTAGES * GBK;
        if (kl < K)
            g_load_stage(As, Bs, Ab, Bb, kl, K, N, tid);
        cp_commit();
        rs = rs + 1; if (rs == GSTAGES) rs = 0;
    }

#pragma unroll
    for (int mt = 0; mt < 4; mt++) {
        int r_lo = by * 128 + wm + mt * 16 + g;
        int r_hi = r_lo + 8;
#pragma unroll
        for (int nt = 0; nt < 8; nt++) {
            int col = bx * 128 + wn + nt * 8 + 2 * tg;
            float b0 = bias[col], b1 = bias[col + 1];
            float v00 = acc[mt][nt][0] + b0, v01 = acc[mt][nt][1] + b1;
            float v10 = acc[mt][nt][2] + b0, v11 = acc[mt][nt][3] + b1;
            if (mode == 2) {
                __half* Ch = (__half*)C;
                int blo = r_lo >> 11, slo = perm32(r_lo & 2047);
                int bhi = r_hi >> 11, shi = perm32(r_hi & 2047);
                Ch[((size_t)blo * N + col)     * SEQ + slo] = __float2half(v00);
                Ch[((size_t)blo * N + col + 1) * SEQ + slo] = __float2half(v01);
                Ch[((size_t)bhi * N + col)     * SEQ + shi] = __float2half(v10);
                Ch[((size_t)bhi * N + col + 1) * SEQ + shi] = __float2half(v11);
            } else {
                *(float2*)(&C[(size_t)r_lo * N + col]) = make_float2(v00, v01);
                *(float2*)(&C[(size_t)r_hi * N + col]) = make_float2(v10, v11);
            }
        }
    }
}

// ---------------------------------------------------------------------------
// Pack q (fp16, scaled, perm32 on k-dim) — rope trig from table
// ---------------------------------------------------------------------------
__global__ __launch_bounds__(256) void pack_q_kernel(
    const float* __restrict__ qC, const float2* __restrict__ rope,
    __half* __restrict__ q)
{
    int gid = blockIdx.x * blockDim.x + threadIdx.x;
    int i = gid & 63;
    int s = (gid >> 6) & (SEQ - 1);
    int h = (gid >> 17) & (NHEADS - 1);
    int b = gid >> 21;

    const float* src = qC + ((size_t)(b * SEQ + s)) * DMODEL + h * HDIM;
    float x1 = src[2 * i], x2 = src[2 * i + 1];

    float2 cssn = rope[s * 64 + i];
    float cs = cssn.x, sn = cssn.y;

    __half* dst = q + (((size_t)(b * NHEADS + h)) * SEQ + s) * QKDIM;
    dst[perm32(2 * i)]       = __float2half(x1 * SCALE);
    dst[perm32(2 * i + 1)]   = __float2half(x2 * SCALE);
    dst[perm32(128 + 2 * i)] = __float2half((x1 * cs - x2 * sn) * SCALE);
    dst[perm32(129 + 2 * i)] = __float2half((x1 * sn + x2 * cs) * SCALE);
}

// ---------------------------------------------------------------------------
// Pack k (fp16, perm32 on k-dim) — rope trig from table
// ---------------------------------------------------------------------------
__global__ __launch_bounds__(256) void pack_k_kernel(
    const float* __restrict__ kC, const float* __restrict__ kr,
    const float2* __restrict__ rope, __half* __restrict__ k)
{
    int gid = blockIdx.x * blockDim.x + threadIdx.x;
    int i = gid & 63;
    int s = (gid >> 6) & (SEQ - 1);
    int h = (gid >> 17) & (NHEADS - 1);
    int b = gid >> 21;

    size_t soff = ((size_t)(b * SEQ + s)) * DMODEL + h * HDIM;
    const float* raw = kC + soff;
    const float* rot = kr + soff;
    float x1 = rot[2 * i], x2 = rot[2 * i + 1];

    float2 cssn = rope[s * 64 + i];
    float cs = cssn.x, sn = cssn.y;

    __half* dst = k + (((size_t)(b * NHEADS + h)) * SEQ + s) * QKDIM;
    dst[perm32(2 * i)]       = __float2half(raw[2 * i]);
    dst[perm32(2 * i + 1)]   = __float2half(raw[2 * i + 1]);
    dst[perm32(128 + 2 * i)] = __float2half(x1 * cs - x2 * sn);
    dst[perm32(129 + 2 * i)] = __float2half(x1 * sn + x2 * cs);
}

// ---------------------------------------------------------------------------
// FP16 flash attention (unchanged from R8).
// ---------------------------------------------------------------------------
#define K_LDH 288
#define V_LDH 96
#define FL_SMEM ((64*K_LDH + 128*V_LDH) * 2)   // 61440 bytes

__global__ __launch_bounds__(128, 2) void flash_f16(
    const __half* __restrict__ q,
    const __half* __restrict__ kk,
    const __half* __restrict__ vT,
    float* __restrict__ ctx)
{
    extern __shared__ __half smh[];
    __half* ks = smh;
    __half* vs = ks + 64 * K_LDH;

    const int tid  = threadIdx.x;
    const int warp = tid >> 5, lane = tid & 31;
    const int g    = lane >> 2;
    const int tg   = lane & 3;
    const int wm   = warp * 16;

    const int qt = 31 - blockIdx.x;
    const int bh = blockIdx.y;
    const int b = bh >> 4, h = bh & 15;

    const __half* vtb_base = vT + ((size_t)b * DMODEL + h * HDIM) * SEQ;
    const __half* kbh      = kk + ((size_t)bh * SEQ) * QKDIM;

    const int rg0 = qt * 64 + wm + g;
    const int rg1 = rg0 + 8;
    uint4 qlo[8], qhi[8];
    {
        const uint4* q0 = (const uint4*)(q + ((size_t)bh * SEQ + rg0) * QKDIM) + tg;
        const uint4* q1 = (const uint4*)(q + ((size_t)bh * SEQ + rg1) * QKDIM) + tg;
#pragma unroll
        for (int kb = 0; kb < 8; kb++) {
            qlo[kb] = q0[kb * 4];
            qhi[kb] = q1[kb * 4];
        }
    }

#pragma unroll
    for (int i = 0; i < 16; i++) {
        int c = tid + 128 * i;
        int r = c >> 5, off = (c & 31) * 8;
        cp_async16(ks + r * K_LDH + off, kbh + (size_t)r * QKDIM + off);
    }
    cp_commit();
#pragma unroll
    for (int i = 0; i < 8; i++) {
        int c = tid + 128 * i;
        int r = c >> 3, off = (c & 7) * 8;
        cp_async16(vs + r * V_LDH + off, vtb_base + (size_t)r * SEQ + off);
    }
    cp_commit();

    float m0 = -1e30f, m1 = -1e30f, l0 = 0.f, l1 = 0.f;
    float oacc[16][4];
#pragma unroll
    for (int nt = 0; nt < 16; nt++)
#pragma unroll
        for (int i = 0; i < 4; i++) oacc[nt][i] = 0.f;

    for (int kt = 0; kt <= qt; kt++) {
        cp_wait1();
        __syncthreads();

        float sacc[8][4];
#pragma unroll
        for (int nt = 0; nt < 8; nt++)
#pragma unroll
            for (int i = 0; i < 4; i++) sacc[nt][i] = 0.f;

#pragma unroll
        for (int kb = 0; kb < 8; kb++) {
            uint4 L = qlo[kb], H = qhi[kb];
#pragma unroll
            for (int nt = 0; nt < 8; nt++) {
                uint4 kv = *(const uint4*)(ks + (8 * nt + g) * K_LDH + kb * 32 + 8 * tg);
                mma_f16(sacc[nt], L.x, H.x, L.y, H.y, kv.x, kv.y);
                mma_f16(sacc[nt], L.z, H.z, L.w, H.w, kv.z, kv.w);
            }
        }

        if (kt == qt) {
            int cb = kt * 64 + 2 * tg;
#pragma unroll
            for (int nt = 0; nt < 8; nt++) {
                int c0 = cb + 8 * nt, c1 = c0 + 1;
                if (c0 > rg0) sacc[nt][0] = -1e30f;
                if (c1 > rg0) sacc[nt][1] = -1e30f;
                if (c0 > rg1) sacc[nt][2] = -1e30f;
                if (c1 > rg1) sacc[nt][3] = -1e30f;
            }
        }

        float tA = -1e30f, tB = -1e30f;
#pragma unroll
        for (int nt = 0; nt < 8; nt++) {
            tA = fmaxf(tA, fmaxf(sacc[nt][0], sacc[nt][1]));
            tB = fmaxf(tB, fmaxf(sacc[nt][2], sacc[nt][3]));
        }
        tA = fmaxf(tA, __shfl_xor_sync(0xffffffffu, tA, 1));
        tA = fmaxf(tA, __shfl_xor_sync(0xffffffffu, tA, 2));
        tB = fmaxf(tB, __shfl_xor_sync(0xffffffffu, tB, 1));
        tB = fmaxf(tB, __shfl_xor_sync(0xffffffffu, tB, 2));

        float mn0 = fmaxf(m0, tA), mn1 = fmaxf(m1, tB);
        float f0 = __expf(m0 - mn0), f1 = __expf(m1 - mn1);
        m0 = mn0; m1 = mn1;

        float sum0 = 0.f, sum1 = 0.f;
        uint32_t ph01[8], ph23[8];
#pragma unroll
        for (int nt = 0; nt < 8; nt++) {
            float p0 = __expf(sacc[nt][0] - mn0);
            float p1 = __expf(sacc[nt][1] - mn0);
            float p2 = __expf(sacc[nt][2] - mn1);
            float p3 = __expf(sacc[nt][3] - mn1);
            sum0 += p0 + p1;
            sum1 += p2 + p3;
            ph01[nt] = h2_as_u32(__floats2half2_rn(p0, p1));
            ph23[nt] = h2_as_u32(__floats2half2_rn(p2, p3));
        }
        sum0 += __shfl_xor_sync(0xffffffffu, sum0, 1);
        sum0 += __shfl_xor_sync(0xffffffffu, sum0, 2);
        sum1 += __shfl_xor_sync(0xffffffffu, sum1, 1);
        sum1 += __shfl_xor_sync(0xffffffffu, sum1, 2);
        l0 = l0 * f0 + sum0;
        l1 = l1 * f1 + sum1;

        __syncthreads();

        if (kt < qt) {
            const __half* kb = kbh + (size_t)(kt + 1) * 64 * QKDIM;
#pragma unroll
            for (int i = 0; i < 16; i++) {
                int c = tid + 128 * i;
                int r = c >> 5, off = (c & 31) * 8;
                cp_async16(ks + r * K_LDH + off, kb + (size_t)r * QKDIM + off);
            }
        }
        cp_commit();

        cp_wait1();
        __syncthreads();

#pragma unroll
        for (int nt = 0; nt < 16; nt++) {
            oacc[nt][0] *= f0; oacc[nt][1] *= f0;
            oacc[nt][2] *= f1; oacc[nt][3] *= f1;
        }
#pragma unroll
        for (int kb = 0; kb < 2; kb++) {
            uint32_t aL0 = ph01[4 * kb + 0], aL1 = ph23[4 * kb + 0];
            uint32_t aL2 = ph01[4 * kb + 1], aL3 = ph23[4 * kb + 1];
            uint32_t aH0 = ph01[4 * kb + 2], aH1 = ph23[4 * kb + 2];
            uint32_t aH2 = ph01[4 * kb + 3], aH3 = ph23[4 * kb + 3];
#pragma unroll
            for (int nt = 0; nt < 16; nt++) {
                uint4 vv = *(const uint4*)(vs + (8 * nt + g) * V_LDH + kb * 32 + 8 * tg);
                mma_f16(oacc[nt], aL0, aL1, aL2, aL3, vv.x, vv.y);
                mma_f16(oacc[nt], aH0, aH1, aH2, aH3, vv.z, vv.w);
            }
        }

        __syncthreads();

        if (kt < qt) {
            const __half* vtb = vtb_base + (size_t)(kt + 1) * 64;
#pragma unroll
            for (int i = 0; i < 8; i++) {
                int c = tid + 128 * i;
                int r = c >> 3, off = (c & 7) * 8;
                cp_async16(vs + r * V_LDH + off, vtb + (size_t)r * SEQ + off);
            }
        }
        cp_commit();
    }

    float inv0 = 1.f / l0, inv1 = 1.f / l1;
    float* o0 = ctx + ((size_t)b * SEQ + rg0) * DMODEL + h * HDIM + 2 * tg;
    float* o1 = ctx + ((size_t)b * SEQ + rg1) * DMODEL + h * HDIM + 2 * tg;
#pragma unroll
    for (int nt = 0; nt < 16; nt++) {
        *(float2*)(o0 + 8 * nt) = make_float2(oacc[nt][0] * inv0, oacc[nt][1] * inv0);
        *(float2*)(o1 + 8 * nt) = make_float2(oacc[nt][2] * inv1, oacc[nt][3] * inv1);
    }
}

// ---------------------------------------------------------------------------
// Launch.  Order chosen so the ncu capture slot (-s 5 -> 6th launch)
// lands on pack_q, directly measuring the pack-cost hypothesis.
// ---------------------------------------------------------------------------
extern "C" void kernel_launch(void* const* d_in, const int* in_sizes, int n_in,
                              void* d_out, int out_size)
{
    const float* h     = (const float*)d_in[0];
    const float* W_DKV = (const float*)d_in[1];
    const float* b_DKV = (const float*)d_in[2];
    const float* W_UK  = (const float*)d_in[3];
    const float* b_UK  = (const float*)d_in[4];
    const float* W_UV  = (const float*)d_in[5];
    const float* b_UV  = (const float*)d_in[6];
    const float* W_DQ  = (const float*)d_in[7];
    const float* b_DQ  = (const float*)d_in[8];
    const float* W_UQ  = (const float*)d_in[9];
    const float* b_UQ  = (const float*)d_in[10];
    const float* W_KR  = (const float*)d_in[11];
    const float* b_KR  = (const float*)d_in[12];
    const float* W_O   = (const float*)d_in[13];
    const float* b_O   = (const float*)d_in[14];

    float* out = (float*)d_out;
    float* cKV = out + OUT_SZ;
    float* kr  = cKV + CKV_SZ;

    float *p_cQ, *p_kC, *p_qC, *p_ctx;
    float2* p_rope;
    __half *p_vT, *p_q, *p_k;
    cudaGetSymbolAddress((void**)&p_cQ,   g_cQ);
    cudaGetSymbolAddress((void**)&p_kC,   g_kC);
    cudaGetSymbolAddress((void**)&p_vT,   g_vT);
    cudaGetSymbolAddress((void**)&p_qC,   g_qC);
    cudaGetSymbolAddress((void**)&p_q,    g_q);
    cudaGetSymbolAddress((void**)&p_k,    g_k);
    cudaGetSymbolAddress((void**)&p_ctx,  g_ctx);
    cudaGetSymbolAddress((void**)&p_rope, g_rope);

    cudaFuncSetAttribute(tf32_gemm_pipe,
                         cudaFuncAttributeMaxDynamicSharedMemorySize, GEMM_SMEM);
    cudaFuncSetAttribute(flash_f16,
                         cudaFuncAttributeMaxDynamicSharedMemorySize, FL_SMEM);

    int pack_threads = BATCH * NHEADS * SEQ * 64;

    // 0: rope table
    rope_table_kernel<<<(SEQ * 64) / 256, 256>>>(p_rope);
    // 1-4: projections needed for q path
    tf32_gemm_pipe<<<dim3(DKV/128,    ROWS/128), 128, GEMM_SMEM>>>(ROWS, DKV,    DMODEL, h,    W_DKV, b_DKV, cKV, 0);
    tf32_gemm_pipe<<<dim3(DMODEL/128, ROWS/128), 128, GEMM_SMEM>>>(ROWS, DMODEL, DMODEL, h,    W_KR,  b_KR,  kr, 0);
    tf32_gemm_pipe<<<dim3(DQ/128,     ROWS/128), 128, GEMM_SMEM>>>(ROWS, DQ,     DMODEL, h,    W_DQ,  b_DQ,  p_cQ, 0);
    tf32_gemm_pipe<<<dim3(DMODEL/128, ROWS/128), 128, GEMM_SMEM>>>(ROWS, DMODEL, DQ,     p_cQ, W_UQ,  b_UQ,  p_qC, 0);
    // 5: pack_q  <-- ncu capture slot (-s 5 -c 1)
    pack_q_kernel<<<pack_threads / 256, 256>>>(p_qC, p_rope, p_q);
    // 6-7: k/v projections
    tf32_gemm_pipe<<<dim3(DMODEL/128, ROWS/128), 128, GEMM_SMEM>>>(ROWS, DMODEL, DKV,    cKV,  W_UK,  b_UK,  p_kC, 0);
    tf32_gemm_pipe<<<dim3(DMODEL/128, ROWS/128), 128, GEMM_SMEM>>>(ROWS, DMODEL, DKV,    cKV,  W_UV,  b_UV,  (float*)p_vT, 2);
    // 8: pack_k
    pack_k_kernel<<<pack_threads / 256, 256>>>(p_kC, kr, p_rope, p_k);
    // 9: attention
    flash_f16<<<dim3(32, BATCH*NHEADS), 128, FL_SMEM>>>(p_q, p_k, p_vT, p_ctx);
    // 10: output projection
    tf32_gemm_pipe<<<dim3(DMODEL/128, ROWS/128), 128, GEMM_SMEM>>>(ROWS, DMODEL, DMODEL, p_ctx, W_O, b_O, out, 0);
}

// round 11
// speedup vs baseline: 2.0729x; 1.6208x over previous
#include <cuda_runtime.h>
#include <cuda_fp16.h>
#include <math.h>
#include <stdint.h>
#include <string.h>

// ---------------------------------------------------------------------------
// Problem constants
// ---------------------------------------------------------------------------
#define BATCH    2
#define SEQ      2048
#define DMODEL   2048
#define DKV      512
#define DQ       1536
#define NHEADS   16
#define HDIM     128
#define ROWS     (BATCH*SEQ)            // 4096
#define QKDIM    256
#define SCALE    0.0625f                // 1/sqrt(256)

#define OUT_SZ   (BATCH*SEQ*DMODEL)
#define CKV_SZ   (BATCH*SEQ*DKV)

// ---------------------------------------------------------------------------
// Scratch
// ---------------------------------------------------------------------------
__device__ float  g_qC [ROWS*DMODEL];
__device__ float  g_kC [ROWS*DMODEL];
__device__ __half g_vT [(size_t)BATCH*DMODEL*SEQ]; // V^T fp16, s-permuted
__device__ __half g_q  [(size_t)BATCH*NHEADS*SEQ*QKDIM]; // fp16, scaled, perm
__device__ __half g_k  [(size_t)BATCH*NHEADS*SEQ*QKDIM]; // fp16, perm
__device__ float2 g_rope[SEQ*64];                  // (cos,sin) per (s,i)

// fp16 GEMM operands (all K-dim perm32)
__device__ __half g_h16  [(size_t)ROWS*DMODEL];
__device__ __half g_cKV16[(size_t)ROWS*DKV];
__device__ __half g_cQ16 [(size_t)ROWS*DQ];
__device__ __half g_ctx16[(size_t)ROWS*DMODEL];
__device__ __half g_wDKV [(size_t)DKV*DMODEL];     // Wt[N,K]
__device__ __half g_wKR  [(size_t)DMODEL*DMODEL];
__device__ __half g_wDQ  [(size_t)DQ*DMODEL];
__device__ __half g_wUQ  [(size_t)DMODEL*DQ];
__device__ __half g_wUK  [(size_t)DMODEL*DKV];
__device__ __half g_wUV  [(size_t)DMODEL*DKV];
__device__ __half g_wWO  [(size_t)DMODEL*DMODEL];

// fragment-order permutation within 32-element blocks of the reduction dim
// (involution: perm32(perm32(k)) == k)
__device__ __forceinline__ int perm32(int k) {
    return (k & ~31) | (((k & 7) >> 1) << 3) | (((k >> 3) & 3) << 1) | (k & 1);
}

// ---------------------------------------------------------------------------
// helpers
// ---------------------------------------------------------------------------
__device__ __forceinline__ uint32_t h2_as_u32(__half2 h) {
    uint32_t u;
    memcpy(&u, &h, 4);
    return u;
}

__device__ __forceinline__ void mma_f16(float c[4],
                                        uint32_t a0, uint32_t a1,
                                        uint32_t a2, uint32_t a3,
                                        uint32_t b0, uint32_t b1) {
    asm volatile(
        "mma.sync.aligned.m16n8k16.row.col.f32.f16.f16.f32 "
        "{%0,%1,%2,%3}, {%4,%5,%6,%7}, {%8,%9}, {%0,%1,%2,%3};\n"
        : "+f"(c[0]), "+f"(c[1]), "+f"(c[2]), "+f"(c[3])
        : "r"(a0), "r"(a1), "r"(a2), "r"(a3), "r"(b0), "r"(b1));
}

__device__ __forceinline__ void cp_async16(void* smem_dst, const void* gsrc) {
    uint32_t sa = (uint32_t)__cvta_generic_to_shared(smem_dst);
    asm volatile("cp.async.cg.shared.global [%0], [%1], 16;\n"
                 :: "r"(sa), "l"(gsrc));
}
__device__ __forceinline__ void cp_commit() {
    asm volatile("cp.async.commit_group;\n" ::: "memory");
}
__device__ __forceinline__ void cp_wait1() {
    asm volatile("cp.async.wait_group 1;\n" ::: "memory");
}

// ---------------------------------------------------------------------------
// Rope table
// ---------------------------------------------------------------------------
__global__ __launch_bounds__(256) void rope_table_kernel(float2* __restrict__ t)
{
    int idx = blockIdx.x * 256 + threadIdx.x;
    int i = idx & 63;
    int s = idx >> 6;
    float inv = powf(10000.0f, -(float)(2 * i) / 128.0f);
    float sn, cs; sincosf((float)s * inv, &sn, &cs);
    t[idx] = make_float2(cs, sn);
}

// ---------------------------------------------------------------------------
// Convert h -> fp16 (perm32 on columns)
// ---------------------------------------------------------------------------
__global__ __launch_bounds__(256) void conv_h_kernel(
    const float* __restrict__ src, __half* __restrict__ dst)
{
    int idx = blockIdx.x * 256 + threadIdx.x;
    int c = idx & (DMODEL - 1);
    int r = idx >> 11;
    dst[(size_t)r * DMODEL + perm32(c)] = __float2half(src[idx]);
}

// ---------------------------------------------------------------------------
// Convert+transpose weight: W[K,N] fp32 -> Wt[N,K] fp16 (perm32 on K)
// ---------------------------------------------------------------------------
__global__ __launch_bounds__(256) void conv_wt_kernel(
    const float* __restrict__ W, __half* __restrict__ Wt, int K, int N)
{
    __shared__ float tile[32][33];
    int k0 = blockIdx.y * 32, n0 = blockIdx.x * 32;
    int tx = threadIdx.x & 31, ty = threadIdx.x >> 5;   // ty: 0..7
#pragma unroll
    for (int j = 0; j < 4; j++)
        tile[ty + 8 * j][tx] = W[(size_t)(k0 + ty + 8 * j) * N + n0 + tx];
    __syncthreads();
#pragma unroll
    for (int j = 0; j < 4; j++) {
        int n = n0 + ty + 8 * j;
        Wt[(size_t)n * K + k0 + perm32(tx)] = __float2half(tile[tx][ty + 8 * j]);
    }
}

// ---------------------------------------------------------------------------
// FP16 tensor-core GEMM: C[M,N] = A[M,K] @ Bt[N,K]^T + bias[N]
// A, Bt fp16 with perm32 K-layout.  BM=BN=128, BK=64, 128 threads (4 warps,
// 2x2 grid, 64x64 warp tile), 2-stage cp.async, 2 CTAs/SM.
// mode bits: 1 = write fp32 C, 2 = write fp16 perm32(col) to Ch,
//            4 = write fp16 transposed s-perm into Ch (vT layout)
// ---------------------------------------------------------------------------
#define HBK    64
#define H_LDH  96                         // halves (48 words == 16 mod 32)
#define HSTAGE (256*H_LDH)                // halves per stage (A 128 + B 128)
#define HGEMM_SMEM (2*HSTAGE*2)           // 98304 bytes

__device__ __forceinline__ void h_load_stage(
    __half* As, __half* Bs,
    const __half* __restrict__ Ab, const __half* __restrict__ Bb,
    int k0, int K, int tid)
{
#pragma unroll
    for (int i = 0; i < 8; i++) {
        int c = tid + 128 * i;            // 1024 chunks of 16B
        int r = c >> 3, off = (c & 7) * 8;
        cp_async16(As + r * H_LDH + off, Ab + (size_t)r * K + k0 + off);
    }
#pragma unroll
    for (int i = 0; i < 8; i++) {
        int c = tid + 128 * i;
        int r = c >> 3, off = (c & 7) * 8;
        cp_async16(Bs + r * H_LDH + off, Bb + (size_t)r * K + k0 + off);
    }
}

__global__ __launch_bounds__(128, 2) void f16_gemm(
    int M, int N, int K,
    const __half* __restrict__ A, const __half* __restrict__ Bt,
    const float* __restrict__ bias,
    float* __restrict__ Cf, __half* __restrict__ Ch, int mode)
{
    extern __shared__ __half hsm[];

    const int tid  = threadIdx.x;
    const int bx   = blockIdx.x, by = blockIdx.y;
    const int warp = tid >> 5, lane = tid & 31;
    const int wm   = (warp >> 1) * 64;
    const int wn   = (warp & 1) * 64;
    const int g    = lane >> 2;
    const int tg   = lane & 3;

    const __half* Ab = A  + (size_t)(by * 128) * K;
    const __half* Bb = Bt + (size_t)(bx * 128) * K;

    float acc[4][8][4];
#pragma unroll
    for (int mt = 0; mt < 4; mt++)
#pragma unroll
        for (int nt = 0; nt < 8; nt++)
#pragma unroll
            for (int i = 0; i < 4; i++) acc[mt][nt][i] = 0.f;

    // prologue: 2 stages
    h_load_stage(hsm, hsm + 128 * H_LDH, Ab, Bb, 0, K, tid);
    cp_commit();
    if (HBK < K)
        h_load_stage(hsm + HSTAGE, hsm + HSTAGE + 128 * H_LDH, Ab, Bb, HBK, K, tid);
    cp_commit();

    int rs = 0;
    for (int k0 = 0; k0 < K; k0 += HBK) {
        cp_wait1();
        __syncthreads();

        __half* As = hsm + rs * HSTAGE;
        __half* Bs = As + 128 * H_LDH;

#pragma unroll
        for (int kb = 0; kb < 2; kb++) {
            uint4 aL[4], aH[4];
#pragma unroll
            for (int mt = 0; mt < 4; mt++) {
                aL[mt] = *(const uint4*)(As + (wm + mt * 16 + g)     * H_LDH + kb * 32 + 8 * tg);
                aH[mt] = *(const uint4*)(As + (wm + mt * 16 + g + 8) * H_LDH + kb * 32 + 8 * tg);
            }
#pragma unroll
            for (int nt = 0; nt < 8; nt++) {
                uint4 bv = *(const uint4*)(Bs + (wn + nt * 8 + g) * H_LDH + kb * 32 + 8 * tg);
#pragma unroll
                for (int mt = 0; mt < 4; mt++) {
                    mma_f16(acc[mt][nt], aL[mt].x, aH[mt].x, aL[mt].y, aH[mt].y, bv.x, bv.y);
                    mma_f16(acc[mt][nt], aL[mt].z, aH[mt].z, aL[mt].w, aH[mt].w, bv.z, bv.w);
                }
            }
        }

        __syncthreads();
        int kl = k0 + 2 * HBK;
        if (kl < K)
            h_load_stage(As, Bs, Ab, Bb, kl, K, tid);
        cp_commit();
        rs ^= 1;
    }

    // epilogue
#pragma unroll
    for (int mt = 0; mt < 4; mt++) {
        int r_lo = by * 128 + wm + mt * 16 + g;
        int r_hi = r_lo + 8;
#pragma unroll
        for (int nt = 0; nt < 8; nt++) {
            int col = bx * 128 + wn + nt * 8 + 2 * tg;
            float b0 = bias[col], b1 = bias[col + 1];
            float v00 = acc[mt][nt][0] + b0, v01 = acc[mt][nt][1] + b1;
            float v10 = acc[mt][nt][2] + b0, v11 = acc[mt][nt][3] + b1;
            if (mode & 1) {
                *(float2*)(&Cf[(size_t)r_lo * N + col]) = make_float2(v00, v01);
                *(float2*)(&Cf[(size_t)r_hi * N + col]) = make_float2(v10, v11);
            }
            if (mode & 2) {
                int pc = perm32(col);
                *(__half2*)(&Ch[(size_t)r_lo * N + pc]) = __floats2half2_rn(v00, v01);
                *(__half2*)(&Ch[(size_t)r_hi * N + pc]) = __floats2half2_rn(v10, v11);
            }
            if (mode & 4) {
                // vT layout: Ch[b][col][perm32(s)]
                int blo = r_lo >> 11, slo = perm32(r_lo & 2047);
                int bhi = r_hi >> 11, shi = perm32(r_hi & 2047);
                Ch[((size_t)blo * N + col)     * SEQ + slo] = __float2half(v00);
                Ch[((size_t)blo * N + col + 1) * SEQ + slo] = __float2half(v01);
                Ch[((size_t)bhi * N + col)     * SEQ + shi] = __float2half(v10);
                Ch[((size_t)bhi * N + col + 1) * SEQ + shi] = __float2half(v11);
            }
        }
    }
}

// ---------------------------------------------------------------------------
// Pack q (fp16, scaled, perm32 on k-dim) — rope trig from table
// ---------------------------------------------------------------------------
__global__ __launch_bounds__(256) void pack_q_kernel(
    const float* __restrict__ qC, const float2* __restrict__ rope,
    __half* __restrict__ q)
{
    int gid = blockIdx.x * blockDim.x + threadIdx.x;
    int i = gid & 63;
    int s = (gid >> 6) & (SEQ - 1);
    int h = (gid >> 17) & (NHEADS - 1);
    int b = gid >> 21;

    const float* src = qC + ((size_t)(b * SEQ + s)) * DMODEL + h * HDIM;
    float x1 = src[2 * i], x2 = src[2 * i + 1];

    float2 cssn = rope[s * 64 + i];
    float cs = cssn.x, sn = cssn.y;

    __half* dst = q + (((size_t)(b * NHEADS + h)) * SEQ + s) * QKDIM;
    dst[perm32(2 * i)]       = __float2half(x1 * SCALE);
    dst[perm32(2 * i + 1)]   = __float2half(x2 * SCALE);
    dst[perm32(128 + 2 * i)] = __float2half((x1 * cs - x2 * sn) * SCALE);
    dst[perm32(129 + 2 * i)] = __float2half((x1 * sn + x2 * cs) * SCALE);
}

// ---------------------------------------------------------------------------
// Pack k (fp16, perm32 on k-dim) — rope trig from table
// ---------------------------------------------------------------------------
__global__ __launch_bounds__(256) void pack_k_kernel(
    const float* __restrict__ kC, const float* __restrict__ kr,
    const float2* __restrict__ rope, __half* __restrict__ k)
{
    int gid = blockIdx.x * blockDim.x + threadIdx.x;
    int i = gid & 63;
    int s = (gid >> 6) & (SEQ - 1);
    int h = (gid >> 17) & (NHEADS - 1);
    int b = gid >> 21;

    size_t soff = ((size_t)(b * SEQ + s)) * DMODEL + h * HDIM;
    const float* raw = kC + soff;
    const float* rot = kr + soff;
    float x1 = rot[2 * i], x2 = rot[2 * i + 1];

    float2 cssn = rope[s * 64 + i];
    float cs = cssn.x, sn = cssn.y;

    __half* dst = k + (((size_t)(b * NHEADS + h)) * SEQ + s) * QKDIM;
    dst[perm32(2 * i)]       = __float2half(raw[2 * i]);
    dst[perm32(2 * i + 1)]   = __float2half(raw[2 * i + 1]);
    dst[perm32(128 + 2 * i)] = __float2half(x1 * cs - x2 * sn);
    dst[perm32(129 + 2 * i)] = __float2half(x1 * sn + x2 * cs);
}

// ---------------------------------------------------------------------------
// FP16 flash attention (R8 structure; epilogue now writes fp16 perm ctx16)
// ---------------------------------------------------------------------------
#define K_LDH 288
#define V_LDH 96
#define FL_SMEM ((64*K_LDH + 128*V_LDH) * 2)   // 61440 bytes

__global__ __launch_bounds__(128, 2) void flash_f16(
    const __half* __restrict__ q,
    const __half* __restrict__ kk,
    const __half* __restrict__ vT,
    __half* __restrict__ ctx16)
{
    extern __shared__ __half smh[];
    __half* ks = smh;
    __half* vs = ks + 64 * K_LDH;

    const int tid  = threadIdx.x;
    const int warp = tid >> 5, lane = tid & 31;
    const int g    = lane >> 2;
    const int tg   = lane & 3;
    const int wm   = warp * 16;

    const int qt = 31 - blockIdx.x;
    const int bh = blockIdx.y;
    const int b = bh >> 4, h = bh & 15;

    const __half* vtb_base = vT + ((size_t)b * DMODEL + h * HDIM) * SEQ;
    const __half* kbh      = kk + ((size_t)bh * SEQ) * QKDIM;

    const int rg0 = qt * 64 + wm + g;
    const int rg1 = rg0 + 8;
    uint4 qlo[8], qhi[8];
    {
        const uint4* q0 = (const uint4*)(q + ((size_t)bh * SEQ + rg0) * QKDIM) + tg;
        const uint4* q1 = (const uint4*)(q + ((size_t)bh * SEQ + rg1) * QKDIM) + tg;
#pragma unroll
        for (int kb = 0; kb < 8; kb++) {
            qlo[kb] = q0[kb * 4];
            qhi[kb] = q1[kb * 4];
        }
    }

#pragma unroll
    for (int i = 0; i < 16; i++) {
        int c = tid + 128 * i;
        int r = c >> 5, off = (c & 31) * 8;
        cp_async16(ks + r * K_LDH + off, kbh + (size_t)r * QKDIM + off);
    }
    cp_commit();
#pragma unroll
    for (int i = 0; i < 8; i++) {
        int c = tid + 128 * i;
        int r = c >> 3, off = (c & 7) * 8;
        cp_async16(vs + r * V_LDH + off, vtb_base + (size_t)r * SEQ + off);
    }
    cp_commit();

    float m0 = -1e30f, m1 = -1e30f, l0 = 0.f, l1 = 0.f;
    float oacc[16][4];
#pragma unroll
    for (int nt = 0; nt < 16; nt++)
#pragma unroll
        for (int i = 0; i < 4; i++) oacc[nt][i] = 0.f;

    for (int kt = 0; kt <= qt; kt++) {
        cp_wait1();
        __syncthreads();

        float sacc[8][4];
#pragma unroll
        for (int nt = 0; nt < 8; nt++)
#pragma unroll
            for (int i = 0; i < 4; i++) sacc[nt][i] = 0.f;

#pragma unroll
        for (int kb = 0; kb < 8; kb++) {
            uint4 L = qlo[kb], H = qhi[kb];
#pragma unroll
            for (int nt = 0; nt < 8; nt++) {
                uint4 kv = *(const uint4*)(ks + (8 * nt + g) * K_LDH + kb * 32 + 8 * tg);
                mma_f16(sacc[nt], L.x, H.x, L.y, H.y, kv.x, kv.y);
                mma_f16(sacc[nt], L.z, H.z, L.w, H.w, kv.z, kv.w);
            }
        }

        if (kt == qt) {
            int cb = kt * 64 + 2 * tg;
#pragma unroll
            for (int nt = 0; nt < 8; nt++) {
                int c0 = cb + 8 * nt, c1 = c0 + 1;
                if (c0 > rg0) sacc[nt][0] = -1e30f;
                if (c1 > rg0) sacc[nt][1] = -1e30f;
                if (c0 > rg1) sacc[nt][2] = -1e30f;
                if (c1 > rg1) sacc[nt][3] = -1e30f;
            }
        }

        float tA = -1e30f, tB = -1e30f;
#pragma unroll
        for (int nt = 0; nt < 8; nt++) {
            tA = fmaxf(tA, fmaxf(sacc[nt][0], sacc[nt][1]));
            tB = fmaxf(tB, fmaxf(sacc[nt][2], sacc[nt][3]));
        }
        tA = fmaxf(tA, __shfl_xor_sync(0xffffffffu, tA, 1));
        tA = fmaxf(tA, __shfl_xor_sync(0xffffffffu, tA, 2));
        tB = fmaxf(tB, __shfl_xor_sync(0xffffffffu, tB, 1));
        tB = fmaxf(tB, __shfl_xor_sync(0xffffffffu, tB, 2));

        float mn0 = fmaxf(m0, tA), mn1 = fmaxf(m1, tB);
        float f0 = __expf(m0 - mn0), f1 = __expf(m1 - mn1);
        m0 = mn0; m1 = mn1;

        float sum0 = 0.f, sum1 = 0.f;
        uint32_t ph01[8], ph23[8];
#pragma unroll
        for (int nt = 0; nt < 8; nt++) {
            float p0 = __expf(sacc[nt][0] - mn0);
            float p1 = __expf(sacc[nt][1] - mn0);
            float p2 = __expf(sacc[nt][2] - mn1);
            float p3 = __expf(sacc[nt][3] - mn1);
            sum0 += p0 + p1;
            sum1 += p2 + p3;
            ph01[nt] = h2_as_u32(__floats2half2_rn(p0, p1));
            ph23[nt] = h2_as_u32(__floats2half2_rn(p2, p3));
        }
        sum0 += __shfl_xor_sync(0xffffffffu, sum0, 1);
        sum0 += __shfl_xor_sync(0xffffffffu, sum0, 2);
        sum1 += __shfl_xor_sync(0xffffffffu, sum1, 1);
        sum1 += __shfl_xor_sync(0xffffffffu, sum1, 2);
        l0 = l0 * f0 + sum0;
        l1 = l1 * f1 + sum1;

        __syncthreads();

        if (kt < qt) {
            const __half* kb = kbh + (size_t)(kt + 1) * 64 * QKDIM;
#pragma unroll
            for (int i = 0; i < 16; i++) {
                int c = tid + 128 * i;
                int r = c >> 5, off = (c & 31) * 8;
                cp_async16(ks + r * K_LDH + off, kb + (size_t)r * QKDIM + off);
            }
        }
        cp_commit();

        cp_wait1();
        __syncthreads();

#pragma unroll
        for (int nt = 0; nt < 16; nt++) {
            oacc[nt][0] *= f0; oacc[nt][1] *= f0;
            oacc[nt][2] *= f1; oacc[nt][3] *= f1;
        }
#pragma unroll
        for (int kb = 0; kb < 2; kb++) {
            uint32_t aL0 = ph01[4 * kb + 0], aL1 = ph23[4 * kb + 0];
            uint32_t aL2 = ph01[4 * kb + 1], aL3 = ph23[4 * kb + 1];
            uint32_t aH0 = ph01[4 * kb + 2], aH1 = ph23[4 * kb + 2];
            uint32_t aH2 = ph01[4 * kb + 3], aH3 = ph23[4 * kb + 3];
#pragma unroll
            for (int nt = 0; nt < 16; nt++) {
                uint4 vv = *(const uint4*)(vs + (8 * nt + g) * V_LDH + kb * 32 + 8 * tg);
                mma_f16(oacc[nt], aL0, aL1, aL2, aL3, vv.x, vv.y);
                mma_f16(oacc[nt], aH0, aH1, aH2, aH3, vv.z, vv.w);
            }
        }

        __syncthreads();

        if (kt < qt) {
            const __half* vtb = vtb_base + (size_t)(kt + 1) * 64;
#pragma unroll
            for (int i = 0; i < 8; i++) {
                int c = tid + 128 * i;
                int r = c >> 3, off = (c & 7) * 8;
                cp_async16(vs + r * V_LDH + off, vtb + (size_t)r * SEQ + off);
            }
        }
        cp_commit();
    }

    // epilogue: fp16 perm32 store for the WO GEMM
    float inv0 = 1.f / l0, inv1 = 1.f / l1;
    __half* o0 = ctx16 + ((size_t)b * SEQ + rg0) * DMODEL + h * HDIM;
    __half* o1 = ctx16 + ((size_t)b * SEQ + rg1) * DMODEL + h * HDIM;
#pragma unroll
    for (int nt = 0; nt < 16; nt++) {
        int c = 8 * nt + 2 * tg;
        int pc = perm32(c);
        *(__half2*)(o0 + pc) = __floats2half2_rn(oacc[nt][0] * inv0, oacc[nt][1] * inv0);
        *(__half2*)(o1 + pc) = __floats2half2_rn(oacc[nt][2] * inv1, oacc[nt][3] * inv1);
    }
}

// ---------------------------------------------------------------------------
// Launch.  Slot 5 (ncu -s 5 -c 1) = first f16_gemm (DKV).
// ---------------------------------------------------------------------------
extern "C" void kernel_launch(void* const* d_in, const int* in_sizes, int n_in,
                              void* d_out, int out_size)
{
    const float* h     = (const float*)d_in[0];
    const float* W_DKV = (const float*)d_in[1];
    const float* b_DKV = (const float*)d_in[2];
    const float* W_UK  = (const float*)d_in[3];
    const float* b_UK  = (const float*)d_in[4];
    const float* W_UV  = (const float*)d_in[5];
    const float* b_UV  = (const float*)d_in[6];
    const float* W_DQ  = (const float*)d_in[7];
    const float* b_DQ  = (const float*)d_in[8];
    const float* W_UQ  = (const float*)d_in[9];
    const float* b_UQ  = (const float*)d_in[10];
    const float* W_KR  = (const float*)d_in[11];
    const float* b_KR  = (const float*)d_in[12];
    const float* W_O   = (const float*)d_in[13];
    const float* b_O   = (const float*)d_in[14];

    float* out = (float*)d_out;
    float* cKV = out + OUT_SZ;
    float* kr  = cKV + CKV_SZ;

    float *p_qC, *p_kC;
    float2* p_rope;
    __half *p_vT, *p_q, *p_k;
    __half *p_h16, *p_cKV16, *p_cQ16, *p_ctx16;
    __half *p_wDKV, *p_wKR, *p_wDQ, *p_wUQ, *p_wUK, *p_wUV, *p_wWO;
    cudaGetSymbolAddress((void**)&p_qC,    g_qC);
    cudaGetSymbolAddress((void**)&p_kC,    g_kC);
    cudaGetSymbolAddress((void**)&p_vT,    g_vT);
    cudaGetSymbolAddress((void**)&p_q,     g_q);
    cudaGetSymbolAddress((void**)&p_k,     g_k);
    cudaGetSymbolAddress((void**)&p_rope,  g_rope);
    cudaGetSymbolAddress((void**)&p_h16,   g_h16);
    cudaGetSymbolAddress((void**)&p_cKV16, g_cKV16);
    cudaGetSymbolAddress((void**)&p_cQ16,  g_cQ16);
    cudaGetSymbolAddress((void**)&p_ctx16, g_ctx16);
    cudaGetSymbolAddress((void**)&p_wDKV,  g_wDKV);
    cudaGetSymbolAddress((void**)&p_wKR,   g_wKR);
    cudaGetSymbolAddress((void**)&p_wDQ,   g_wDQ);
    cudaGetSymbolAddress((void**)&p_wUQ,   g_wUQ);
    cudaGetSymbolAddress((void**)&p_wUK,   g_wUK);
    cudaGetSymbolAddress((void**)&p_wUV,   g_wUV);
    cudaGetSymbolAddress((void**)&p_wWO,   g_wWO);

    cudaFuncSetAttribute(f16_gemm,
                         cudaFuncAttributeMaxDynamicSharedMemorySize, HGEMM_SMEM);
    cudaFuncSetAttribute(flash_f16,
                         cudaFuncAttributeMaxDynamicSharedMemorySize, FL_SMEM);

    int pack_threads = BATCH * NHEADS * SEQ * 64;

    // 0: rope table
    rope_table_kernel<<<(SEQ * 64) / 256, 256>>>(p_rope);
    // 1: h -> fp16 perm
    conv_h_kernel<<<(ROWS * DMODEL) / 256, 256>>>(h, p_h16);
    // 2-4: weight transposes needed first
    conv_wt_kernel<<<dim3(DKV/32,    DMODEL/32), 256>>>(W_DKV, p_wDKV, DMODEL, DKV);
    conv_wt_kernel<<<dim3(DMODEL/32, DMODEL/32), 256>>>(W_KR,  p_wKR,  DMODEL, DMODEL);
    conv_wt_kernel<<<dim3(DQ/32,     DMODEL/32), 256>>>(W_DQ,  p_wDQ,  DMODEL, DQ);
    // 5: DKV GEMM  <-- ncu capture slot
    f16_gemm<<<dim3(DKV/128,    ROWS/128), 128, HGEMM_SMEM>>>(ROWS, DKV,    DMODEL, p_h16, p_wDKV, b_DKV, cKV, p_cKV16, 3);
    // remaining weight transposes
    conv_wt_kernel<<<dim3(DMODEL/32, DQ/32),     256>>>(W_UQ, p_wUQ, DQ,  DMODEL);
    conv_wt_kernel<<<dim3(DMODEL/32, DKV/32),    256>>>(W_UK, p_wUK, DKV, DMODEL);
    conv_wt_kernel<<<dim3(DMODEL/32, DKV/32),    256>>>(W_UV, p_wUV, DKV, DMODEL);
    conv_wt_kernel<<<dim3(DMODEL/32, DMODEL/32), 256>>>(W_O,  p_wWO, DMODEL, DMODEL);
    // projections
    f16_gemm<<<dim3(DMODEL/128, ROWS/128), 128, HGEMM_SMEM>>>(ROWS, DMODEL, DMODEL, p_h16,   p_wKR, b_KR, kr,   (__half*)0, 1);
    f16_gemm<<<dim3(DQ/128,     ROWS/128), 128, HGEMM_SMEM>>>(ROWS, DQ,     DMODEL, p_h16,   p_wDQ, b_DQ, (float*)0, p_cQ16, 2);
    f16_gemm<<<dim3(DMODEL/128, ROWS/128), 128, HGEMM_SMEM>>>(ROWS, DMODEL, DQ,     p_cQ16,  p_wUQ, b_UQ, p_qC, (__half*)0, 1);
    pack_q_kernel<<<pack_threads / 256, 256>>>(p_qC, p_rope, p_q);
    f16_gemm<<<dim3(DMODEL/128, ROWS/128), 128, HGEMM_SMEM>>>(ROWS, DMODEL, DKV,    p_cKV16, p_wUK, b_UK, p_kC, (__half*)0, 1);
    f16_gemm<<<dim3(DMODEL/128, ROWS/128), 128, HGEMM_SMEM>>>(ROWS, DMODEL, DKV,    p_cKV16, p_wUV, b_UV, (float*)0, p_vT, 4);
    pack_k_kernel<<<pack_threads / 256, 256>>>(p_kC, kr, p_rope, p_k);
    // attention
    flash_f16<<<dim3(32, BATCH*NHEADS), 128, FL_SMEM>>>(p_q, p_k, p_vT, p_ctx16);
    // output projection
    f16_gemm<<<dim3(DMODEL/128, ROWS/128), 128, HGEMM_SMEM>>>(ROWS, DMODEL, DMODEL, p_ctx16, p_wWO, b_O, out, (__half*)0, 1);
}